// round 4
// baseline (speedup 1.0000x reference)
#include <cuda_runtime.h>
#include <math.h>

#define NN 50000
#define EE 800000
#define ET (EE + NN)
#define FIN 128
#define HID 64
#define H1 8
#define C1 (H1 * HID)   // 512
#define GG 64
#define NEG_SLOPE 0.2f
#define EPS 1e-16f

// ---------------- scratch (device globals; no allocations allowed) ----------
__device__ float g_h1[(size_t)NN * C1];   // layer1 GEMM output [N,512]
__device__ float g_ha[(size_t)NN * C1];   // layer1 activated output [N,512]
__device__ float g_as1[NN * H1];
__device__ float g_ad1[NN * H1];
__device__ float g_h2[NN * HID];          // layer2 GEMM output [N,64]
__device__ float g_as2[NN];
__device__ float g_ad2[NN];
__device__ float g_out2[NN * HID];        // layer2 aggregated output [N,64]
__device__ int   g_deg[NN];
__device__ int   g_fill[NN];
__device__ int   g_rowptr[NN + 1];
__device__ int   g_esrc[ET];

// ---------------- helpers ----------------
__global__ void k_zero() {
    int i = blockIdx.x * blockDim.x + threadIdx.x;
    if (i < NN) { g_deg[i] = 0; g_fill[i] = 0; }
}

__global__ void k_count(const int* __restrict__ ei) {
    int i = blockIdx.x * blockDim.x + threadIdx.x;
    if (i >= ET) return;
    int dst = (i < EE) ? ei[EE + i] : (i - EE);
    atomicAdd(&g_deg[dst], 1);
}

// exclusive scan of g_deg -> g_rowptr, single block of 1024 threads
__global__ void k_scan() {
    __shared__ int s[1024];
    __shared__ int base_sh;
    if (threadIdx.x == 0) base_sh = 0;
    __syncthreads();
    for (int start = 0; start < NN; start += 1024) {
        int i = start + threadIdx.x;
        int v = (i < NN) ? g_deg[i] : 0;
        s[threadIdx.x] = v;
        __syncthreads();
        for (int off = 1; off < 1024; off <<= 1) {
            int t = (threadIdx.x >= off) ? s[threadIdx.x - off] : 0;
            __syncthreads();
            s[threadIdx.x] += t;
            __syncthreads();
        }
        int base = base_sh;
        if (i < NN) g_rowptr[i] = base + s[threadIdx.x] - v;
        __syncthreads();
        if (threadIdx.x == 0) base_sh = base + s[1023];
        __syncthreads();
    }
    if (threadIdx.x == 0) g_rowptr[NN] = base_sh;
}

__global__ void k_scatter(const int* __restrict__ ei) {
    int i = blockIdx.x * blockDim.x + threadIdx.x;
    if (i >= ET) return;
    int src, dst;
    if (i < EE) { src = ei[i]; dst = ei[EE + i]; }
    else        { src = i - EE; dst = i - EE; }
    int pos = g_rowptr[dst] + atomicAdd(&g_fill[dst], 1);
    g_esrc[pos] = src;
}

// sort each dst-segment by src for deterministic accumulation order
__global__ void k_sortseg() {
    int d = blockIdx.x * blockDim.x + threadIdx.x;
    if (d >= NN) return;
    int r0 = g_rowptr[d], r1 = g_rowptr[d + 1];
    int len = r1 - r0;
    if (len <= 1) return;
    if (len <= 64) {
        int buf[64];
        for (int i = 0; i < len; i++) buf[i] = g_esrc[r0 + i];
        for (int i = 1; i < len; i++) {
            int key = buf[i], j = i - 1;
            while (j >= 0 && buf[j] > key) { buf[j + 1] = buf[j]; j--; }
            buf[j + 1] = key;
        }
        for (int i = 0; i < len; i++) g_esrc[r0 + i] = buf[i];
    } else {
        for (int i = r0 + 1; i < r1; i++) {
            int key = g_esrc[i], j = i - 1;
            while (j >= r0 && g_esrc[j] > key) { g_esrc[j + 1] = g_esrc[j]; j--; }
            g_esrc[j + 1] = key;
        }
    }
}

// ---------------- SGEMM: C[M,Nn] = A[M,K] @ B[K,Nn], 128x64 tile -----------
template<bool LAYER1>
__global__ void k_sgemm(const float* __restrict__ Aarg, const float* __restrict__ B,
                        int M, int K, int Nn) {
    const float* __restrict__ A = LAYER1 ? Aarg : (const float*)g_ha;
    float* __restrict__ C       = LAYER1 ? (float*)g_h1 : (float*)g_h2;

    __shared__ float As[16][132];
    __shared__ float Bs[16][64];
    int tid = threadIdx.x;
    int tx = tid & 15, ty = tid >> 4;           // 16x16 thread grid
    int bm = blockIdx.y * 128, bn = blockIdx.x * 64;
    float acc[8][4];
    #pragma unroll
    for (int i = 0; i < 8; i++)
        #pragma unroll
        for (int j = 0; j < 4; j++) acc[i][j] = 0.f;

    for (int k0 = 0; k0 < K; k0 += 16) {
        #pragma unroll
        for (int i = 0; i < 8; i++) {           // A: 128x16 = 2048 elems
            int e = tid + i * 256;
            int m = e >> 4, kk = e & 15;
            int gm = bm + m;
            As[kk][m] = (gm < M) ? A[(size_t)gm * K + k0 + kk] : 0.f;
        }
        #pragma unroll
        for (int i = 0; i < 4; i++) {           // B: 16x64 = 1024 elems
            int e = tid + i * 256;
            int kk = e >> 6, n = e & 63;
            int gn = bn + n;
            Bs[kk][n] = (gn < Nn) ? B[(size_t)(k0 + kk) * Nn + gn] : 0.f;
        }
        __syncthreads();
        #pragma unroll
        for (int kk = 0; kk < 16; kk++) {
            float4 a0 = *(const float4*)&As[kk][ty * 8];
            float4 a1 = *(const float4*)&As[kk][ty * 8 + 4];
            float4 b0 = *(const float4*)&Bs[kk][tx * 4];
            float a[8] = {a0.x, a0.y, a0.z, a0.w, a1.x, a1.y, a1.z, a1.w};
            float b[4] = {b0.x, b0.y, b0.z, b0.w};
            #pragma unroll
            for (int i = 0; i < 8; i++)
                #pragma unroll
                for (int j = 0; j < 4; j++) acc[i][j] = fmaf(a[i], b[j], acc[i][j]);
        }
        __syncthreads();
    }
    #pragma unroll
    for (int i = 0; i < 8; i++) {
        int gm = bm + ty * 8 + i;
        if (gm >= M) continue;
        #pragma unroll
        for (int j = 0; j < 4; j++) {
            int gn = bn + tx * 4 + j;
            if (gn < Nn) C[(size_t)gm * Nn + gn] = acc[i][j];
        }
    }
}

// ---------------- attention scores ----------------
__global__ void k_att1(const float* __restrict__ att_s, const float* __restrict__ att_d) {
    int w = (blockIdx.x * blockDim.x + threadIdx.x) >> 5;
    int lane = threadIdx.x & 31;
    if (w >= NN * H1) return;
    int n = w >> 3, h = w & 7;
    const float* hp = g_h1 + (size_t)n * C1 + h * HID;
    float v0 = hp[lane], v1 = hp[lane + 32];
    float s = v0 * att_s[h * HID + lane] + v1 * att_s[h * HID + lane + 32];
    float d = v0 * att_d[h * HID + lane] + v1 * att_d[h * HID + lane + 32];
    #pragma unroll
    for (int off = 16; off; off >>= 1) {
        s += __shfl_down_sync(0xffffffffu, s, off);
        d += __shfl_down_sync(0xffffffffu, d, off);
    }
    if (lane == 0) { g_as1[n * H1 + h] = s; g_ad1[n * H1 + h] = d; }
}

__global__ void k_att2(const float* __restrict__ att_s, const float* __restrict__ att_d) {
    int n = (blockIdx.x * blockDim.x + threadIdx.x) >> 5;
    int lane = threadIdx.x & 31;
    if (n >= NN) return;
    const float* hp = g_h2 + (size_t)n * HID;
    float v0 = hp[lane], v1 = hp[lane + 32];
    float s = v0 * att_s[lane] + v1 * att_s[lane + 32];
    float d = v0 * att_d[lane] + v1 * att_d[lane + 32];
    #pragma unroll
    for (int off = 16; off; off >>= 1) {
        s += __shfl_down_sync(0xffffffffu, s, off);
        d += __shfl_down_sync(0xffffffffu, d, off);
    }
    if (lane == 0) { g_as2[n] = s; g_ad2[n] = d; }
}

__device__ __forceinline__ float lrelu(float e) {
    return e > 0.f ? e : NEG_SLOPE * e;
}

// ---------------- fused segment softmax + aggregation --------------------
// layer 1: one warp per (dst, head); output = elu(agg + bias)
__global__ void k_gather1(const float* __restrict__ bias) {
    int w = (blockIdx.x * blockDim.x + threadIdx.x) >> 5;
    int lane = threadIdx.x & 31;
    if (w >= NN * H1) return;
    int d = w >> 3, h = w & 7;
    float ad = g_ad1[d * H1 + h];
    int r0 = g_rowptr[d], r1 = g_rowptr[d + 1];

    float emax = -INFINITY;
    for (int i = r0; i < r1; i++) {
        int s = g_esrc[i];
        emax = fmaxf(emax, lrelu(g_as1[s * H1 + h] + ad));
    }
    float denom = 0.f, a0 = 0.f, a1 = 0.f;
    for (int i = r0; i < r1; i++) {
        int s = g_esrc[i];
        float e = lrelu(g_as1[s * H1 + h] + ad);
        float wgt = __expf(e - emax);
        denom += wgt;
        const float* hp = g_h1 + (size_t)s * C1 + h * HID;
        a0 = fmaf(wgt, hp[lane], a0);
        a1 = fmaf(wgt, hp[lane + 32], a1);
    }
    float inv = 1.f / (denom + EPS);
    int ob = d * C1 + h * HID;
    float o0 = a0 * inv + bias[h * HID + lane];
    float o1 = a1 * inv + bias[h * HID + lane + 32];
    g_ha[(size_t)ob + lane]      = o0 > 0.f ? o0 : expm1f(o0);
    g_ha[(size_t)ob + 32 + lane] = o1 > 0.f ? o1 : expm1f(o1);
}

// layer 2: one warp per dst; 1 head, no activation
__global__ void k_gather2(const float* __restrict__ bias) {
    int d = (blockIdx.x * blockDim.x + threadIdx.x) >> 5;
    int lane = threadIdx.x & 31;
    if (d >= NN) return;
    float ad = g_ad2[d];
    int r0 = g_rowptr[d], r1 = g_rowptr[d + 1];

    float emax = -INFINITY;
    for (int i = r0; i < r1; i++) {
        int s = g_esrc[i];
        emax = fmaxf(emax, lrelu(g_as2[s] + ad));
    }
    float denom = 0.f, a0 = 0.f, a1 = 0.f;
    for (int i = r0; i < r1; i++) {
        int s = g_esrc[i];
        float e = lrelu(g_as2[s] + ad);
        float wgt = __expf(e - emax);
        denom += wgt;
        const float* hp = g_h2 + (size_t)s * HID;
        a0 = fmaf(wgt, hp[lane], a0);
        a1 = fmaf(wgt, hp[lane + 32], a1);
    }
    float inv = 1.f / (denom + EPS);
    g_out2[(size_t)d * HID + lane]      = a0 * inv + bias[lane];
    g_out2[(size_t)d * HID + lane + 32] = a1 * inv + bias[lane + 32];
}

// ---------------- global mean pool + final linear ----------------
__device__ __forceinline__ int lb32(const int* a, int n, int v) {
    int lo = 0, hi = n;
    while (lo < hi) { int mid = (lo + hi) >> 1; if (a[mid] < v) lo = mid + 1; else hi = mid; }
    return lo;
}

__global__ void k_pool(const int* __restrict__ batch,
                       const float* __restrict__ linW,
                       const float* __restrict__ linb,
                       float* __restrict__ out) {
    __shared__ float sm[256];
    int g = blockIdx.x;                     // 64 blocks
    int lo = lb32(batch, NN, g);
    int hi = lb32(batch, NN, g + 1);
    int c = threadIdx.x & 63;
    int sub = threadIdx.x >> 6;             // 4 node lanes
    float acc = 0.f;
    for (int n = lo + sub; n < hi; n += 4)
        acc += g_out2[(size_t)n * HID + c];
    sm[threadIdx.x] = acc;
    __syncthreads();
    if (threadIdx.x < 64) {
        float v = sm[threadIdx.x] + sm[threadIdx.x + 64] + sm[threadIdx.x + 128] + sm[threadIdx.x + 192];
        sm[threadIdx.x] = v * linW[threadIdx.x];
    }
    __syncthreads();
    if (threadIdx.x < 32) {
        float v = sm[threadIdx.x] + sm[threadIdx.x + 32];
        #pragma unroll
        for (int off = 16; off; off >>= 1) v += __shfl_down_sync(0xffffffffu, v, off);
        if (threadIdx.x == 0) {
            float cnt = (float)(hi - lo);
            out[g] = v / fmaxf(cnt, 1.f) + linb[0];
        }
    }
}

// ---------------- launch ----------------
extern "C" void kernel_launch(void* const* d_in, const int* in_sizes, int n_in,
                              void* d_out, int out_size) {
    const float* x     = (const float*)d_in[0];
    const int*   ei    = (const int*)d_in[1];      // int32 per harness metadata
    const int*   batch = (const int*)d_in[2];      // int32 per harness metadata
    const float* W1   = (const float*)d_in[3];
    const float* as1  = (const float*)d_in[4];
    const float* ad1  = (const float*)d_in[5];
    const float* b1   = (const float*)d_in[6];
    const float* W2   = (const float*)d_in[7];
    const float* as2  = (const float*)d_in[8];
    const float* ad2  = (const float*)d_in[9];
    const float* b2   = (const float*)d_in[10];
    const float* linW = (const float*)d_in[11];
    const float* linb = (const float*)d_in[12];
    float* out = (float*)d_out;
    (void)in_sizes; (void)n_in; (void)out_size;

    // CSR build
    k_zero<<<(NN + 255) / 256, 256>>>();
    k_count<<<(ET + 255) / 256, 256>>>(ei);
    k_scan<<<1, 1024>>>();
    k_scatter<<<(ET + 255) / 256, 256>>>(ei);
    k_sortseg<<<(NN + 255) / 256, 256>>>();

    // layer 1
    {
        dim3 grid(C1 / 64, (NN + 127) / 128);
        k_sgemm<true><<<grid, 256>>>(x, W1, NN, FIN, C1);
    }
    k_att1<<<(NN * H1 + 7) / 8, 256>>>(as1, ad1);
    k_gather1<<<(NN * H1 + 7) / 8, 256>>>(b1);

    // layer 2
    {
        dim3 grid(HID / 64, (NN + 127) / 128);
        k_sgemm<false><<<grid, 256>>>(nullptr, W2, NN, C1, HID);
    }
    k_att2<<<(NN + 7) / 8, 256>>>(as2, ad2);
    k_gather2<<<(NN + 7) / 8, 256>>>(b2);

    // pool + linear
    k_pool<<<GG, 256>>>(batch, linW, linb, out);
}

// round 5
// speedup vs baseline: 1.0890x; 1.0890x over previous
#include <cuda_runtime.h>
#include <math.h>

#define NN 50000
#define EE 800000
#define ET (EE + NN)
#define FIN 128
#define HID 64
#define H1 8
#define C1 (H1 * HID)   // 512
#define GG 64
#define NEG_SLOPE 0.2f
#define EPS 1e-16f

// ---------------- scratch (device globals; no allocations allowed) ----------
__device__ float g_h1[(size_t)NN * C1];   // layer1 GEMM output [N,512]
__device__ float g_ha[(size_t)NN * C1];   // layer1 activated output [N,512]
__device__ float g_as1[NN * H1];
__device__ float g_ad1[NN * H1];
__device__ float g_h2[NN * HID];          // layer2 GEMM output [N,64]
__device__ float g_as2[NN];
__device__ float g_ad2[NN];
__device__ float g_out2[NN * HID];        // layer2 aggregated output [N,64]
__device__ int   g_deg[NN];
__device__ int   g_fill[NN];
__device__ int   g_rowptr[NN + 1];
__device__ int   g_esrc[ET];

// ---------------- CSR build ----------------
__global__ void k_zero() {
    int i = blockIdx.x * blockDim.x + threadIdx.x;
    if (i < NN) { g_deg[i] = 0; g_fill[i] = 0; }
}

__global__ void k_count(const int* __restrict__ ei) {
    int i = blockIdx.x * blockDim.x + threadIdx.x;
    if (i >= ET) return;
    int dst = (i < EE) ? ei[EE + i] : (i - EE);
    atomicAdd(&g_deg[dst], 1);
}

__global__ void k_scan() {
    __shared__ int s[1024];
    __shared__ int base_sh;
    if (threadIdx.x == 0) base_sh = 0;
    __syncthreads();
    for (int start = 0; start < NN; start += 1024) {
        int i = start + threadIdx.x;
        int v = (i < NN) ? g_deg[i] : 0;
        s[threadIdx.x] = v;
        __syncthreads();
        for (int off = 1; off < 1024; off <<= 1) {
            int t = (threadIdx.x >= off) ? s[threadIdx.x - off] : 0;
            __syncthreads();
            s[threadIdx.x] += t;
            __syncthreads();
        }
        int base = base_sh;
        if (i < NN) g_rowptr[i] = base + s[threadIdx.x] - v;
        __syncthreads();
        if (threadIdx.x == 0) base_sh = base + s[1023];
        __syncthreads();
    }
    if (threadIdx.x == 0) g_rowptr[NN] = base_sh;
}

__global__ void k_scatter(const int* __restrict__ ei) {
    int i = blockIdx.x * blockDim.x + threadIdx.x;
    if (i >= ET) return;
    int src, dst;
    if (i < EE) { src = ei[i]; dst = ei[EE + i]; }
    else        { src = i - EE; dst = i - EE; }
    int pos = g_rowptr[dst] + atomicAdd(&g_fill[dst], 1);
    g_esrc[pos] = src;
}

__global__ void k_sortseg() {
    int d = blockIdx.x * blockDim.x + threadIdx.x;
    if (d >= NN) return;
    int r0 = g_rowptr[d], r1 = g_rowptr[d + 1];
    int len = r1 - r0;
    if (len <= 1) return;
    if (len <= 64) {
        int buf[64];
        for (int i = 0; i < len; i++) buf[i] = g_esrc[r0 + i];
        for (int i = 1; i < len; i++) {
            int key = buf[i], j = i - 1;
            while (j >= 0 && buf[j] > key) { buf[j + 1] = buf[j]; j--; }
            buf[j + 1] = key;
        }
        for (int i = 0; i < len; i++) g_esrc[r0 + i] = buf[i];
    } else {
        for (int i = r0 + 1; i < r1; i++) {
            int key = g_esrc[i], j = i - 1;
            while (j >= r0 && g_esrc[j] > key) { g_esrc[j + 1] = g_esrc[j]; j--; }
            g_esrc[j + 1] = key;
        }
    }
}

// ---------------- GEMM1: g_h1[50000,512] = x[50000,128] @ W1[128,512] ------
// 128x128 tile, BK=8, 256 threads, 8x8 per thread, double-buffered.
__global__ void __launch_bounds__(256, 2)
k_gemm1(const float* __restrict__ A, const float* __restrict__ B) {
    float* __restrict__ C = g_h1;
    __shared__ float As[2][8][132];
    __shared__ float Bs[2][8][128];
    int tid = threadIdx.x;
    int tx = tid & 15, ty = tid >> 4;
    int bm = blockIdx.y * 128, bn = blockIdx.x * 128;

    int ar = tid >> 1;            // A row within tile (0..127)
    int ak = (tid & 1) * 4;       // k quad (0 or 4)
    int br = tid >> 5;            // B k-row (0..7)
    int bc = (tid & 31) * 4;      // B col quad

    float4 aReg, bReg;
    // preload tile 0
    {
        int gm = bm + ar;
        aReg = (gm < NN) ? *(const float4*)&A[(size_t)gm * FIN + ak]
                         : make_float4(0.f, 0.f, 0.f, 0.f);
        bReg = *(const float4*)&B[(size_t)br * C1 + bn + bc];
        As[0][ak + 0][ar] = aReg.x; As[0][ak + 1][ar] = aReg.y;
        As[0][ak + 2][ar] = aReg.z; As[0][ak + 3][ar] = aReg.w;
        *(float4*)&Bs[0][br][bc] = bReg;
    }
    __syncthreads();

    float acc[8][8];
    #pragma unroll
    for (int i = 0; i < 8; i++)
        #pragma unroll
        for (int j = 0; j < 8; j++) acc[i][j] = 0.f;

    const int NT = FIN / 8;   // 16 k-tiles
    for (int t = 0; t < NT; t++) {
        int buf = t & 1;
        if (t < NT - 1) {
            int k0 = (t + 1) * 8;
            int gm = bm + ar;
            aReg = (gm < NN) ? *(const float4*)&A[(size_t)gm * FIN + k0 + ak]
                             : make_float4(0.f, 0.f, 0.f, 0.f);
            bReg = *(const float4*)&B[(size_t)(k0 + br) * C1 + bn + bc];
        }
        #pragma unroll
        for (int k = 0; k < 8; k++) {
            float4 a0 = *(const float4*)&As[buf][k][ty * 8];
            float4 a1 = *(const float4*)&As[buf][k][ty * 8 + 4];
            float4 b0 = *(const float4*)&Bs[buf][k][tx * 8];
            float4 b1 = *(const float4*)&Bs[buf][k][tx * 8 + 4];
            float av[8] = {a0.x, a0.y, a0.z, a0.w, a1.x, a1.y, a1.z, a1.w};
            float bv[8] = {b0.x, b0.y, b0.z, b0.w, b1.x, b1.y, b1.z, b1.w};
            #pragma unroll
            for (int i = 0; i < 8; i++)
                #pragma unroll
                for (int j = 0; j < 8; j++) acc[i][j] = fmaf(av[i], bv[j], acc[i][j]);
        }
        if (t < NT - 1) {
            int nb = buf ^ 1;
            As[nb][ak + 0][ar] = aReg.x; As[nb][ak + 1][ar] = aReg.y;
            As[nb][ak + 2][ar] = aReg.z; As[nb][ak + 3][ar] = aReg.w;
            *(float4*)&Bs[nb][br][bc] = bReg;
            __syncthreads();
        }
    }
    #pragma unroll
    for (int i = 0; i < 8; i++) {
        int gm = bm + ty * 8 + i;
        if (gm >= NN) continue;
        float4 o0 = make_float4(acc[i][0], acc[i][1], acc[i][2], acc[i][3]);
        float4 o1 = make_float4(acc[i][4], acc[i][5], acc[i][6], acc[i][7]);
        *(float4*)&C[(size_t)gm * C1 + bn + tx * 8]     = o0;
        *(float4*)&C[(size_t)gm * C1 + bn + tx * 8 + 4] = o1;
    }
}

// ---------------- GEMM2: g_h2[50000,64] = g_ha[50000,512] @ W2[512,64] -----
// 128x64 tile, BK=8, 128 threads, 8x8 per thread, double-buffered.
__global__ void __launch_bounds__(128, 4)
k_gemm2(const float* __restrict__ B) {
    const float* __restrict__ A = (const float*)g_ha;
    float* __restrict__ C = g_h2;
    __shared__ float As[2][8][132];
    __shared__ float Bs[2][8][64];
    int tid = threadIdx.x;
    int tx = tid & 7, ty = tid >> 3;     // 16x8 thread grid
    int bm = blockIdx.y * 128;

    int bkb = tid >> 4;                  // B k-row (0..7)
    int bcc = (tid & 15) * 4;            // B col quad

    float4 aReg[2], bReg;
    {
        #pragma unroll
        for (int i = 0; i < 2; i++) {
            int e = tid + i * 128;
            int row = e >> 1, k4 = (e & 1) * 4;
            int gm = bm + row;
            aReg[i] = (gm < NN) ? *(const float4*)&A[(size_t)gm * C1 + k4]
                                : make_float4(0.f, 0.f, 0.f, 0.f);
        }
        bReg = *(const float4*)&B[(size_t)bkb * HID + bcc];
        #pragma unroll
        for (int i = 0; i < 2; i++) {
            int e = tid + i * 128;
            int row = e >> 1, k4 = (e & 1) * 4;
            As[0][k4 + 0][row] = aReg[i].x; As[0][k4 + 1][row] = aReg[i].y;
            As[0][k4 + 2][row] = aReg[i].z; As[0][k4 + 3][row] = aReg[i].w;
        }
        *(float4*)&Bs[0][bkb][bcc] = bReg;
    }
    __syncthreads();

    float acc[8][8];
    #pragma unroll
    for (int i = 0; i < 8; i++)
        #pragma unroll
        for (int j = 0; j < 8; j++) acc[i][j] = 0.f;

    const int NT = C1 / 8;   // 64 k-tiles
    for (int t = 0; t < NT; t++) {
        int buf = t & 1;
        if (t < NT - 1) {
            int k0 = (t + 1) * 8;
            #pragma unroll
            for (int i = 0; i < 2; i++) {
                int e = tid + i * 128;
                int row = e >> 1, k4 = (e & 1) * 4;
                int gm = bm + row;
                aReg[i] = (gm < NN) ? *(const float4*)&A[(size_t)gm * C1 + k0 + k4]
                                    : make_float4(0.f, 0.f, 0.f, 0.f);
            }
            bReg = *(const float4*)&B[(size_t)(k0 + bkb) * HID + bcc];
        }
        #pragma unroll
        for (int k = 0; k < 8; k++) {
            float4 a0 = *(const float4*)&As[buf][k][ty * 8];
            float4 a1 = *(const float4*)&As[buf][k][ty * 8 + 4];
            float4 b0 = *(const float4*)&Bs[buf][k][tx * 8];
            float4 b1 = *(const float4*)&Bs[buf][k][tx * 8 + 4];
            float av[8] = {a0.x, a0.y, a0.z, a0.w, a1.x, a1.y, a1.z, a1.w};
            float bv[8] = {b0.x, b0.y, b0.z, b0.w, b1.x, b1.y, b1.z, b1.w};
            #pragma unroll
            for (int i = 0; i < 8; i++)
                #pragma unroll
                for (int j = 0; j < 8; j++) acc[i][j] = fmaf(av[i], bv[j], acc[i][j]);
        }
        if (t < NT - 1) {
            int nb = buf ^ 1;
            #pragma unroll
            for (int i = 0; i < 2; i++) {
                int e = tid + i * 128;
                int row = e >> 1, k4 = (e & 1) * 4;
                As[nb][k4 + 0][row] = aReg[i].x; As[nb][k4 + 1][row] = aReg[i].y;
                As[nb][k4 + 2][row] = aReg[i].z; As[nb][k4 + 3][row] = aReg[i].w;
            }
            *(float4*)&Bs[nb][bkb][bcc] = bReg;
            __syncthreads();
        }
    }
    #pragma unroll
    for (int i = 0; i < 8; i++) {
        int gm = bm + ty * 8 + i;
        if (gm >= NN) continue;
        float4 o0 = make_float4(acc[i][0], acc[i][1], acc[i][2], acc[i][3]);
        float4 o1 = make_float4(acc[i][4], acc[i][5], acc[i][6], acc[i][7]);
        *(float4*)&C[(size_t)gm * HID + tx * 8]     = o0;
        *(float4*)&C[(size_t)gm * HID + tx * 8 + 4] = o1;
    }
}

// ---------------- attention scores ----------------
__global__ void k_att1(const float* __restrict__ att_s, const float* __restrict__ att_d) {
    int w = (blockIdx.x * blockDim.x + threadIdx.x) >> 5;
    int lane = threadIdx.x & 31;
    if (w >= NN * H1) return;
    int n = w >> 3, h = w & 7;
    const float* hp = g_h1 + (size_t)n * C1 + h * HID;
    float v0 = hp[lane], v1 = hp[lane + 32];
    float s = v0 * att_s[h * HID + lane] + v1 * att_s[h * HID + lane + 32];
    float d = v0 * att_d[h * HID + lane] + v1 * att_d[h * HID + lane + 32];
    #pragma unroll
    for (int off = 16; off; off >>= 1) {
        s += __shfl_down_sync(0xffffffffu, s, off);
        d += __shfl_down_sync(0xffffffffu, d, off);
    }
    if (lane == 0) { g_as1[n * H1 + h] = s; g_ad1[n * H1 + h] = d; }
}

__global__ void k_att2(const float* __restrict__ att_s, const float* __restrict__ att_d) {
    int n = (blockIdx.x * blockDim.x + threadIdx.x) >> 5;
    int lane = threadIdx.x & 31;
    if (n >= NN) return;
    const float* hp = g_h2 + (size_t)n * HID;
    float v0 = hp[lane], v1 = hp[lane + 32];
    float s = v0 * att_s[lane] + v1 * att_s[lane + 32];
    float d = v0 * att_d[lane] + v1 * att_d[lane + 32];
    #pragma unroll
    for (int off = 16; off; off >>= 1) {
        s += __shfl_down_sync(0xffffffffu, s, off);
        d += __shfl_down_sync(0xffffffffu, d, off);
    }
    if (lane == 0) { g_as2[n] = s; g_ad2[n] = d; }
}

__device__ __forceinline__ float lrelu(float e) {
    return e > 0.f ? e : NEG_SLOPE * e;
}

// ---------------- fused segment softmax + aggregation --------------------
// Single pass: softmax is shift-invariant and |scores| are O(1) here, so
// exp() without max subtraction is safe in fp32 (overflow needs e > 88).
__global__ void k_gather1(const float* __restrict__ bias) {
    int w = (blockIdx.x * blockDim.x + threadIdx.x) >> 5;
    int lane = threadIdx.x & 31;
    if (w >= NN * H1) return;
    int d = w >> 3, h = w & 7;
    float ad = g_ad1[d * H1 + h];
    int r0 = g_rowptr[d], r1 = g_rowptr[d + 1];

    float den = 0.f, a0 = 0.f, a1 = 0.f;
    for (int i = r0; i < r1; i++) {
        int s = __ldg(&g_esrc[i]);
        float e = lrelu(__ldg(&g_as1[s * H1 + h]) + ad);
        float wgt = __expf(e);
        den += wgt;
        const float* hp = g_h1 + (size_t)s * C1 + h * HID;
        a0 = fmaf(wgt, __ldg(&hp[lane]), a0);
        a1 = fmaf(wgt, __ldg(&hp[lane + 32]), a1);
    }
    float inv = 1.f / (den + EPS);
    int ob = d * C1 + h * HID;
    float o0 = a0 * inv + bias[h * HID + lane];
    float o1 = a1 * inv + bias[h * HID + lane + 32];
    g_ha[(size_t)ob + lane]      = o0 > 0.f ? o0 : expm1f(o0);
    g_ha[(size_t)ob + 32 + lane] = o1 > 0.f ? o1 : expm1f(o1);
}

__global__ void k_gather2(const float* __restrict__ bias) {
    int d = (blockIdx.x * blockDim.x + threadIdx.x) >> 5;
    int lane = threadIdx.x & 31;
    if (d >= NN) return;
    float ad = g_ad2[d];
    int r0 = g_rowptr[d], r1 = g_rowptr[d + 1];

    float den = 0.f, a0 = 0.f, a1 = 0.f;
    for (int i = r0; i < r1; i++) {
        int s = __ldg(&g_esrc[i]);
        float e = lrelu(__ldg(&g_as2[s]) + ad);
        float wgt = __expf(e);
        den += wgt;
        const float* hp = g_h2 + (size_t)s * HID;
        a0 = fmaf(wgt, __ldg(&hp[lane]), a0);
        a1 = fmaf(wgt, __ldg(&hp[lane + 32]), a1);
    }
    float inv = 1.f / (den + EPS);
    g_out2[(size_t)d * HID + lane]      = a0 * inv + bias[lane];
    g_out2[(size_t)d * HID + lane + 32] = a1 * inv + bias[lane + 32];
}

// ---------------- global mean pool + final linear ----------------
__device__ __forceinline__ int lb32(const int* a, int n, int v) {
    int lo = 0, hi = n;
    while (lo < hi) { int mid = (lo + hi) >> 1; if (a[mid] < v) lo = mid + 1; else hi = mid; }
    return lo;
}

__global__ void k_pool(const int* __restrict__ batch,
                       const float* __restrict__ linW,
                       const float* __restrict__ linb,
                       float* __restrict__ out) {
    __shared__ float sm[256];
    int g = blockIdx.x;
    int lo = lb32(batch, NN, g);
    int hi = lb32(batch, NN, g + 1);
    int c = threadIdx.x & 63;
    int sub = threadIdx.x >> 6;
    float acc = 0.f;
    for (int n = lo + sub; n < hi; n += 4)
        acc += g_out2[(size_t)n * HID + c];
    sm[threadIdx.x] = acc;
    __syncthreads();
    if (threadIdx.x < 64) {
        float v = sm[threadIdx.x] + sm[threadIdx.x + 64] + sm[threadIdx.x + 128] + sm[threadIdx.x + 192];
        sm[threadIdx.x] = v * linW[threadIdx.x];
    }
    __syncthreads();
    if (threadIdx.x < 32) {
        float v = sm[threadIdx.x] + sm[threadIdx.x + 32];
        #pragma unroll
        for (int off = 16; off; off >>= 1) v += __shfl_down_sync(0xffffffffu, v, off);
        if (threadIdx.x == 0) {
            float cnt = (float)(hi - lo);
            out[g] = v / fmaxf(cnt, 1.f) + linb[0];
        }
    }
}

// ---------------- launch ----------------
extern "C" void kernel_launch(void* const* d_in, const int* in_sizes, int n_in,
                              void* d_out, int out_size) {
    const float* x     = (const float*)d_in[0];
    const int*   ei    = (const int*)d_in[1];
    const int*   batch = (const int*)d_in[2];
    const float* W1   = (const float*)d_in[3];
    const float* as1  = (const float*)d_in[4];
    const float* ad1  = (const float*)d_in[5];
    const float* b1   = (const float*)d_in[6];
    const float* W2   = (const float*)d_in[7];
    const float* as2  = (const float*)d_in[8];
    const float* ad2  = (const float*)d_in[9];
    const float* b2   = (const float*)d_in[10];
    const float* linW = (const float*)d_in[11];
    const float* linb = (const float*)d_in[12];
    float* out = (float*)d_out;
    (void)in_sizes; (void)n_in; (void)out_size;

    // CSR build
    k_zero<<<(NN + 255) / 256, 256>>>();
    k_count<<<(ET + 255) / 256, 256>>>(ei);
    k_scan<<<1, 1024>>>();
    k_scatter<<<(ET + 255) / 256, 256>>>(ei);
    k_sortseg<<<(NN + 255) / 256, 256>>>();

    // layer 1
    {
        dim3 grid(C1 / 128, (NN + 127) / 128);
        k_gemm1<<<grid, 256>>>(x, W1);
    }
    k_att1<<<(NN * H1 + 7) / 8, 256>>>(as1, ad1);
    k_gather1<<<(NN * H1 + 7) / 8, 256>>>(b1);

    // layer 2
    {
        dim3 grid(1, (NN + 127) / 128);
        k_gemm2<<<grid, 128>>>(W2);
    }
    k_att2<<<(NN + 7) / 8, 256>>>(as2, ad2);
    k_gather2<<<(NN + 7) / 8, 256>>>(b2);

    // pool + linear
    k_pool<<<GG, 256>>>(batch, linW, linb, out);
}

// round 6
// speedup vs baseline: 1.2615x; 1.1584x over previous
#include <cuda_runtime.h>
#include <cuda_fp16.h>
#include <math.h>

#define NN 50000
#define EE 800000
#define ET (EE + NN)
#define FIN 128
#define HID 64
#define H1 8
#define C1 (H1 * HID)   // 512
#define GG 64
#define NEG_SLOPE 0.2f
#define EPS 1e-16f

// ---------------- scratch (device globals; no allocations allowed) ----------
__device__ __half g_h1h[(size_t)NN * C1];  // layer1 GEMM output, fp16 messages
__device__ float  g_ha[(size_t)NN * C1];   // layer1 activated output [N,512] fp32
__device__ __half g_h2h[(size_t)NN * HID]; // layer2 GEMM output, fp16 messages
__device__ float  g_as1[NN * H1];
__device__ float  g_ad1[NN * H1];
__device__ float  g_as2[NN];
__device__ float  g_ad2[NN];
__device__ float  g_out2[NN * HID];
__device__ int    g_deg[NN];
__device__ int    g_fill[NN];
__device__ int    g_rowptr[NN + 1];
__device__ int    g_esrc[ET];

// ---------------- CSR build ----------------
__global__ void k_zero() {
    int i = blockIdx.x * blockDim.x + threadIdx.x;
    if (i < NN) { g_deg[i] = 0; g_fill[i] = 0; }
}

__global__ void k_count(const int* __restrict__ ei) {
    int i = blockIdx.x * blockDim.x + threadIdx.x;
    if (i >= ET) return;
    int dst = (i < EE) ? ei[EE + i] : (i - EE);
    atomicAdd(&g_deg[dst], 1);
}

__global__ void k_scan() {
    __shared__ int s[1024];
    __shared__ int base_sh;
    if (threadIdx.x == 0) base_sh = 0;
    __syncthreads();
    for (int start = 0; start < NN; start += 1024) {
        int i = start + threadIdx.x;
        int v = (i < NN) ? g_deg[i] : 0;
        s[threadIdx.x] = v;
        __syncthreads();
        for (int off = 1; off < 1024; off <<= 1) {
            int t = (threadIdx.x >= off) ? s[threadIdx.x - off] : 0;
            __syncthreads();
            s[threadIdx.x] += t;
            __syncthreads();
        }
        int base = base_sh;
        if (i < NN) g_rowptr[i] = base + s[threadIdx.x] - v;
        __syncthreads();
        if (threadIdx.x == 0) base_sh = base + s[1023];
        __syncthreads();
    }
    if (threadIdx.x == 0) g_rowptr[NN] = base_sh;
}

__global__ void k_scatter(const int* __restrict__ ei) {
    int i = blockIdx.x * blockDim.x + threadIdx.x;
    if (i >= ET) return;
    int src, dst;
    if (i < EE) { src = ei[i]; dst = ei[EE + i]; }
    else        { src = i - EE; dst = i - EE; }
    int pos = g_rowptr[dst] + atomicAdd(&g_fill[dst], 1);
    g_esrc[pos] = src;
}

__global__ void k_sortseg() {
    int d = blockIdx.x * blockDim.x + threadIdx.x;
    if (d >= NN) return;
    int r0 = g_rowptr[d], r1 = g_rowptr[d + 1];
    int len = r1 - r0;
    if (len <= 1) return;
    if (len <= 64) {
        int buf[64];
        for (int i = 0; i < len; i++) buf[i] = g_esrc[r0 + i];
        for (int i = 1; i < len; i++) {
            int key = buf[i], j = i - 1;
            while (j >= 0 && buf[j] > key) { buf[j + 1] = buf[j]; j--; }
            buf[j + 1] = key;
        }
        for (int i = 0; i < len; i++) g_esrc[r0 + i] = buf[i];
    } else {
        for (int i = r0 + 1; i < r1; i++) {
            int key = g_esrc[i], j = i - 1;
            while (j >= r0 && g_esrc[j] > key) { g_esrc[j + 1] = g_esrc[j]; j--; }
            g_esrc[j + 1] = key;
        }
    }
}

// ---------------- GEMM1 + att scores: h1h[50000,512] = x @ W1 --------------
// 128x128 tile, BK=8, 256 threads, 8x8/thread, double-buffered.
// Epilogue: fp16 store + per-row/head att_src,att_dst dots via width-8 shuffles.
__global__ void __launch_bounds__(256, 2)
k_gemm1(const float* __restrict__ A, const float* __restrict__ B,
        const float* __restrict__ att_s, const float* __restrict__ att_d) {
    __shared__ float As[2][8][132];
    __shared__ float Bs[2][8][128];
    int tid = threadIdx.x;
    int tx = tid & 15, ty = tid >> 4;
    int bm = blockIdx.y * 128, bn = blockIdx.x * 128;

    int ar = tid >> 1;
    int ak = (tid & 1) * 4;
    int br = tid >> 5;
    int bc = (tid & 31) * 4;

    float4 aReg, bReg;
    {
        int gm = bm + ar;
        aReg = (gm < NN) ? *(const float4*)&A[(size_t)gm * FIN + ak]
                         : make_float4(0.f, 0.f, 0.f, 0.f);
        bReg = *(const float4*)&B[(size_t)br * C1 + bn + bc];
        As[0][ak + 0][ar] = aReg.x; As[0][ak + 1][ar] = aReg.y;
        As[0][ak + 2][ar] = aReg.z; As[0][ak + 3][ar] = aReg.w;
        *(float4*)&Bs[0][br][bc] = bReg;
    }
    __syncthreads();

    float acc[8][8];
    #pragma unroll
    for (int i = 0; i < 8; i++)
        #pragma unroll
        for (int j = 0; j < 8; j++) acc[i][j] = 0.f;

    const int NT = FIN / 8;
    for (int t = 0; t < NT; t++) {
        int buf = t & 1;
        if (t < NT - 1) {
            int k0 = (t + 1) * 8;
            int gm = bm + ar;
            aReg = (gm < NN) ? *(const float4*)&A[(size_t)gm * FIN + k0 + ak]
                             : make_float4(0.f, 0.f, 0.f, 0.f);
            bReg = *(const float4*)&B[(size_t)(k0 + br) * C1 + bn + bc];
        }
        #pragma unroll
        for (int k = 0; k < 8; k++) {
            float4 a0 = *(const float4*)&As[buf][k][ty * 8];
            float4 a1 = *(const float4*)&As[buf][k][ty * 8 + 4];
            float4 b0 = *(const float4*)&Bs[buf][k][tx * 8];
            float4 b1 = *(const float4*)&Bs[buf][k][tx * 8 + 4];
            float av[8] = {a0.x, a0.y, a0.z, a0.w, a1.x, a1.y, a1.z, a1.w};
            float bv[8] = {b0.x, b0.y, b0.z, b0.w, b1.x, b1.y, b1.z, b1.w};
            #pragma unroll
            for (int i = 0; i < 8; i++)
                #pragma unroll
                for (int j = 0; j < 8; j++) acc[i][j] = fmaf(av[i], bv[j], acc[i][j]);
        }
        if (t < NT - 1) {
            int nb = buf ^ 1;
            As[nb][ak + 0][ar] = aReg.x; As[nb][ak + 1][ar] = aReg.y;
            As[nb][ak + 2][ar] = aReg.z; As[nb][ak + 3][ar] = aReg.w;
            *(float4*)&Bs[nb][br][bc] = bReg;
            __syncthreads();
        }
    }

    // fp16 store
    #pragma unroll
    for (int i = 0; i < 8; i++) {
        int gm = bm + ty * 8 + i;
        if (gm >= NN) continue;
        union { uint4 u; __half2 h[4]; } pk;
        pk.h[0] = __floats2half2_rn(acc[i][0], acc[i][1]);
        pk.h[1] = __floats2half2_rn(acc[i][2], acc[i][3]);
        pk.h[2] = __floats2half2_rn(acc[i][4], acc[i][5]);
        pk.h[3] = __floats2half2_rn(acc[i][6], acc[i][7]);
        *(uint4*)&g_h1h[(size_t)gm * C1 + bn + tx * 8] = pk.u;
    }

    // attention score epilogue: head = (bn>>6) + (tx>>3); width-8 shuffle reduce
    int hglob = (bn >> 6) + (tx >> 3);
    const float* asv = att_s + hglob * HID + (tx & 7) * 8;
    const float* adv = att_d + hglob * HID + (tx & 7) * 8;
    #pragma unroll
    for (int i = 0; i < 8; i++) {
        float sp = 0.f, dp = 0.f;
        #pragma unroll
        for (int j = 0; j < 8; j++) {
            sp = fmaf(acc[i][j], asv[j], sp);
            dp = fmaf(acc[i][j], adv[j], dp);
        }
        #pragma unroll
        for (int off = 4; off; off >>= 1) {
            sp += __shfl_down_sync(0xffffffffu, sp, off, 8);
            dp += __shfl_down_sync(0xffffffffu, dp, off, 8);
        }
        if ((tx & 7) == 0) {
            int gm = bm + ty * 8 + i;
            if (gm < NN) { g_as1[gm * H1 + hglob] = sp; g_ad1[gm * H1 + hglob] = dp; }
        }
    }
}

// ---------------- GEMM2 + att scores: h2h[50000,64] = g_ha @ W2 ------------
// 128x64 tile, BK=8, 128 threads, 8x8/thread, double-buffered.
__global__ void __launch_bounds__(128, 4)
k_gemm2(const float* __restrict__ B,
        const float* __restrict__ att_s, const float* __restrict__ att_d) {
    const float* __restrict__ A = (const float*)g_ha;
    __shared__ float As[2][8][132];
    __shared__ float Bs[2][8][64];
    int tid = threadIdx.x;
    int tx = tid & 7, ty = tid >> 3;
    int bm = blockIdx.y * 128;

    int bkb = tid >> 4;
    int bcc = (tid & 15) * 4;

    float4 aReg[2], bReg;
    {
        #pragma unroll
        for (int i = 0; i < 2; i++) {
            int e = tid + i * 128;
            int row = e >> 1, k4 = (e & 1) * 4;
            int gm = bm + row;
            aReg[i] = (gm < NN) ? *(const float4*)&A[(size_t)gm * C1 + k4]
                                : make_float4(0.f, 0.f, 0.f, 0.f);
        }
        bReg = *(const float4*)&B[(size_t)bkb * HID + bcc];
        #pragma unroll
        for (int i = 0; i < 2; i++) {
            int e = tid + i * 128;
            int row = e >> 1, k4 = (e & 1) * 4;
            As[0][k4 + 0][row] = aReg[i].x; As[0][k4 + 1][row] = aReg[i].y;
            As[0][k4 + 2][row] = aReg[i].z; As[0][k4 + 3][row] = aReg[i].w;
        }
        *(float4*)&Bs[0][bkb][bcc] = bReg;
    }
    __syncthreads();

    float acc[8][8];
    #pragma unroll
    for (int i = 0; i < 8; i++)
        #pragma unroll
        for (int j = 0; j < 8; j++) acc[i][j] = 0.f;

    const int NT = C1 / 8;
    for (int t = 0; t < NT; t++) {
        int buf = t & 1;
        if (t < NT - 1) {
            int k0 = (t + 1) * 8;
            #pragma unroll
            for (int i = 0; i < 2; i++) {
                int e = tid + i * 128;
                int row = e >> 1, k4 = (e & 1) * 4;
                int gm = bm + row;
                aReg[i] = (gm < NN) ? *(const float4*)&A[(size_t)gm * C1 + k0 + k4]
                                    : make_float4(0.f, 0.f, 0.f, 0.f);
            }
            bReg = *(const float4*)&B[(size_t)(k0 + bkb) * HID + bcc];
        }
        #pragma unroll
        for (int k = 0; k < 8; k++) {
            float4 a0 = *(const float4*)&As[buf][k][ty * 8];
            float4 a1 = *(const float4*)&As[buf][k][ty * 8 + 4];
            float4 b0 = *(const float4*)&Bs[buf][k][tx * 8];
            float4 b1 = *(const float4*)&Bs[buf][k][tx * 8 + 4];
            float av[8] = {a0.x, a0.y, a0.z, a0.w, a1.x, a1.y, a1.z, a1.w};
            float bv[8] = {b0.x, b0.y, b0.z, b0.w, b1.x, b1.y, b1.z, b1.w};
            #pragma unroll
            for (int i = 0; i < 8; i++)
                #pragma unroll
                for (int j = 0; j < 8; j++) acc[i][j] = fmaf(av[i], bv[j], acc[i][j]);
        }
        if (t < NT - 1) {
            int nb = buf ^ 1;
            #pragma unroll
            for (int i = 0; i < 2; i++) {
                int e = tid + i * 128;
                int row = e >> 1, k4 = (e & 1) * 4;
                As[nb][k4 + 0][row] = aReg[i].x; As[nb][k4 + 1][row] = aReg[i].y;
                As[nb][k4 + 2][row] = aReg[i].z; As[nb][k4 + 3][row] = aReg[i].w;
            }
            *(float4*)&Bs[nb][bkb][bcc] = bReg;
            __syncthreads();
        }
    }

    // fp16 store
    #pragma unroll
    for (int i = 0; i < 8; i++) {
        int gm = bm + ty * 8 + i;
        if (gm >= NN) continue;
        union { uint4 u; __half2 h[4]; } pk;
        pk.h[0] = __floats2half2_rn(acc[i][0], acc[i][1]);
        pk.h[1] = __floats2half2_rn(acc[i][2], acc[i][3]);
        pk.h[2] = __floats2half2_rn(acc[i][4], acc[i][5]);
        pk.h[3] = __floats2half2_rn(acc[i][6], acc[i][7]);
        *(uint4*)&g_h2h[(size_t)gm * HID + tx * 8] = pk.u;
    }

    // attention scores (single head), width-8 shuffle reduce
    const float* asv = att_s + tx * 8;
    const float* adv = att_d + tx * 8;
    #pragma unroll
    for (int i = 0; i < 8; i++) {
        float sp = 0.f, dp = 0.f;
        #pragma unroll
        for (int j = 0; j < 8; j++) {
            sp = fmaf(acc[i][j], asv[j], sp);
            dp = fmaf(acc[i][j], adv[j], dp);
        }
        #pragma unroll
        for (int off = 4; off; off >>= 1) {
            sp += __shfl_down_sync(0xffffffffu, sp, off, 8);
            dp += __shfl_down_sync(0xffffffffu, dp, off, 8);
        }
        if (tx == 0) {
            int gm = bm + ty * 8 + i;
            if (gm < NN) { g_as2[gm] = sp; g_ad2[gm] = dp; }
        }
    }
}

__device__ __forceinline__ float lrelu(float e) {
    return e > 0.f ? e : NEG_SLOPE * e;
}

// ---------------- gather1: one block per dst, warp h = head h --------------
// Single-pass softmax (scores O(1), shift-invariant; no overflow possible).
__global__ void __launch_bounds__(256, 8)
k_gather1(const float* __restrict__ bias) {
    int d = blockIdx.x;
    int h = threadIdx.x >> 5, lane = threadIdx.x & 31;
    int r0 = g_rowptr[d], r1 = g_rowptr[d + 1];
    float ad = g_ad1[d * H1 + h];
    __shared__ int s_src[64];

    float den = 0.f, a0 = 0.f, a1 = 0.f;
    for (int base = r0; base < r1; base += 64) {
        int cl = min(64, r1 - base);
        __syncthreads();
        for (int i = threadIdx.x; i < cl; i += 256) s_src[i] = g_esrc[base + i];
        __syncthreads();
        for (int i = 0; i < cl; i++) {
            int s = s_src[i];
            float e = lrelu(__ldg(&g_as1[s * H1 + h]) + ad);
            float w = __expf(e);
            den += w;
            __half2 v = ((const __half2*)(g_h1h + (size_t)s * C1 + h * HID))[lane];
            float2 vf = __half22float2(v);
            a0 = fmaf(w, vf.x, a0);
            a1 = fmaf(w, vf.y, a1);
        }
    }
    float inv = 1.f / (den + EPS);
    int c0 = h * HID + 2 * lane;
    float o0 = a0 * inv + bias[c0];
    float o1 = a1 * inv + bias[c0 + 1];
    o0 = o0 > 0.f ? o0 : expm1f(o0);
    o1 = o1 > 0.f ? o1 : expm1f(o1);
    *(float2*)&g_ha[(size_t)d * C1 + c0] = make_float2(o0, o1);
}

// ---------------- gather2: one warp per dst --------------------------------
__global__ void k_gather2(const float* __restrict__ bias) {
    int d = (blockIdx.x * blockDim.x + threadIdx.x) >> 5;
    int lane = threadIdx.x & 31;
    if (d >= NN) return;
    float ad = g_ad2[d];
    int r0 = g_rowptr[d], r1 = g_rowptr[d + 1];

    float den = 0.f, a0 = 0.f, a1 = 0.f;
    for (int i = r0; i < r1; i++) {
        int s = __ldg(&g_esrc[i]);
        float e = lrelu(__ldg(&g_as2[s]) + ad);
        float w = __expf(e);
        den += w;
        __half2 v = ((const __half2*)(g_h2h + (size_t)s * HID))[lane];
        float2 vf = __half22float2(v);
        a0 = fmaf(w, vf.x, a0);
        a1 = fmaf(w, vf.y, a1);
    }
    float inv = 1.f / (den + EPS);
    int c0 = 2 * lane;
    g_out2[(size_t)d * HID + c0]     = a0 * inv + bias[c0];
    g_out2[(size_t)d * HID + c0 + 1] = a1 * inv + bias[c0 + 1];
}

// ---------------- global mean pool + final linear ----------------
__device__ __forceinline__ int lb32(const int* a, int n, int v) {
    int lo = 0, hi = n;
    while (lo < hi) { int mid = (lo + hi) >> 1; if (a[mid] < v) lo = mid + 1; else hi = mid; }
    return lo;
}

__global__ void k_pool(const int* __restrict__ batch,
                       const float* __restrict__ linW,
                       const float* __restrict__ linb,
                       float* __restrict__ out) {
    __shared__ float sm[256];
    int g = blockIdx.x;
    int lo = lb32(batch, NN, g);
    int hi = lb32(batch, NN, g + 1);
    int c = threadIdx.x & 63;
    int sub = threadIdx.x >> 6;
    float acc = 0.f;
    for (int n = lo + sub; n < hi; n += 4)
        acc += g_out2[(size_t)n * HID + c];
    sm[threadIdx.x] = acc;
    __syncthreads();
    if (threadIdx.x < 64) {
        float v = sm[threadIdx.x] + sm[threadIdx.x + 64] + sm[threadIdx.x + 128] + sm[threadIdx.x + 192];
        sm[threadIdx.x] = v * linW[threadIdx.x];
    }
    __syncthreads();
    if (threadIdx.x < 32) {
        float v = sm[threadIdx.x] + sm[threadIdx.x + 32];
        #pragma unroll
        for (int off = 16; off; off >>= 1) v += __shfl_down_sync(0xffffffffu, v, off);
        if (threadIdx.x == 0) {
            float cnt = (float)(hi - lo);
            out[g] = v / fmaxf(cnt, 1.f) + linb[0];
        }
    }
}

// ---------------- launch ----------------
extern "C" void kernel_launch(void* const* d_in, const int* in_sizes, int n_in,
                              void* d_out, int out_size) {
    const float* x     = (const float*)d_in[0];
    const int*   ei    = (const int*)d_in[1];
    const int*   batch = (const int*)d_in[2];
    const float* W1   = (const float*)d_in[3];
    const float* as1  = (const float*)d_in[4];
    const float* ad1  = (const float*)d_in[5];
    const float* b1   = (const float*)d_in[6];
    const float* W2   = (const float*)d_in[7];
    const float* as2  = (const float*)d_in[8];
    const float* ad2  = (const float*)d_in[9];
    const float* b2   = (const float*)d_in[10];
    const float* linW = (const float*)d_in[11];
    const float* linb = (const float*)d_in[12];
    float* out = (float*)d_out;
    (void)in_sizes; (void)n_in; (void)out_size;

    // CSR build
    k_zero<<<(NN + 255) / 256, 256>>>();
    k_count<<<(ET + 255) / 256, 256>>>(ei);
    k_scan<<<1, 1024>>>();
    k_scatter<<<(ET + 255) / 256, 256>>>(ei);
    k_sortseg<<<(NN + 255) / 256, 256>>>();

    // layer 1 (GEMM + fused att scores), then fused softmax-gather
    {
        dim3 grid(C1 / 128, (NN + 127) / 128);
        k_gemm1<<<grid, 256>>>(x, W1, as1, ad1);
    }
    k_gather1<<<NN, 256>>>(b1);

    // layer 2
    {
        dim3 grid(1, (NN + 127) / 128);
        k_gemm2<<<grid, 128>>>(W2, as2, ad2);
    }
    k_gather2<<<(NN + 7) / 8, 256>>>(b2);

    // pool + linear
    k_pool<<<GG, 256>>>(batch, linW, linb, out);
}

// round 7
// speedup vs baseline: 1.7411x; 1.3802x over previous
#include <cuda_runtime.h>
#include <cuda_fp16.h>
#include <mma.h>
#include <math.h>

using namespace nvcuda;

#define NN 50000
#define EE 800000
#define ET (EE + NN)
#define FIN 128
#define HID 64
#define H1 8
#define C1 (H1 * HID)   // 512
#define GG 64
#define NEG_SLOPE 0.2f
#define EPS 1e-16f

// ---------------- scratch (device globals; no allocations allowed) ----------
__device__ __half g_xh[(size_t)NN * FIN];   // x in fp16
__device__ __half g_w1h[FIN * C1];          // W1 fp16
__device__ __half g_w2h[C1 * HID];          // W2 fp16
__device__ __half g_h1h[(size_t)NN * C1];   // layer1 GEMM output fp16
__device__ __half g_hah[(size_t)NN * C1];   // layer1 activated output fp16
__device__ __half g_h2h[(size_t)NN * HID];  // layer2 GEMM output fp16
__device__ float  g_as1[NN * H1];
__device__ float  g_ad1[NN * H1];
__device__ float  g_as2[NN];
__device__ float  g_ad2[NN];
__device__ float  g_out2[NN * HID];
__device__ int    g_deg[NN];
__device__ int    g_fill[NN];
__device__ int    g_rowptr[NN + 1];
__device__ int    g_esrc[ET];

// ---------------- CSR build ----------------
__global__ void k_zero() {
    int i = blockIdx.x * blockDim.x + threadIdx.x;
    if (i < NN) { g_deg[i] = 0; g_fill[i] = 0; }
}

__global__ void k_count(const int* __restrict__ ei) {
    int i = blockIdx.x * blockDim.x + threadIdx.x;
    if (i >= ET) return;
    int dst = (i < EE) ? ei[EE + i] : (i - EE);
    atomicAdd(&g_deg[dst], 1);
}

__global__ void k_scan() {
    __shared__ int s[1024];
    __shared__ int base_sh;
    if (threadIdx.x == 0) base_sh = 0;
    __syncthreads();
    for (int start = 0; start < NN; start += 1024) {
        int i = start + threadIdx.x;
        int v = (i < NN) ? g_deg[i] : 0;
        s[threadIdx.x] = v;
        __syncthreads();
        for (int off = 1; off < 1024; off <<= 1) {
            int t = (threadIdx.x >= off) ? s[threadIdx.x - off] : 0;
            __syncthreads();
            s[threadIdx.x] += t;
            __syncthreads();
        }
        int base = base_sh;
        if (i < NN) g_rowptr[i] = base + s[threadIdx.x] - v;
        __syncthreads();
        if (threadIdx.x == 0) base_sh = base + s[1023];
        __syncthreads();
    }
    if (threadIdx.x == 0) g_rowptr[NN] = base_sh;
}

__global__ void k_scatter(const int* __restrict__ ei) {
    int i = blockIdx.x * blockDim.x + threadIdx.x;
    if (i >= ET) return;
    int src, dst;
    if (i < EE) { src = ei[i]; dst = ei[EE + i]; }
    else        { src = i - EE; dst = i - EE; }
    int pos = g_rowptr[dst] + atomicAdd(&g_fill[dst], 1);
    g_esrc[pos] = src;
}

__global__ void k_sortseg() {
    int d = blockIdx.x * blockDim.x + threadIdx.x;
    if (d >= NN) return;
    int r0 = g_rowptr[d], r1 = g_rowptr[d + 1];
    int len = r1 - r0;
    if (len <= 1) return;
    if (len <= 64) {
        int buf[64];
        for (int i = 0; i < len; i++) buf[i] = g_esrc[r0 + i];
        for (int i = 1; i < len; i++) {
            int key = buf[i], j = i - 1;
            while (j >= 0 && buf[j] > key) { buf[j + 1] = buf[j]; j--; }
            buf[j + 1] = key;
        }
        for (int i = 0; i < len; i++) g_esrc[r0 + i] = buf[i];
    } else {
        for (int i = r0 + 1; i < r1; i++) {
            int key = g_esrc[i], j = i - 1;
            while (j >= r0 && g_esrc[j] > key) { g_esrc[j + 1] = g_esrc[j]; j--; }
            g_esrc[j + 1] = key;
        }
    }
}

// ---------------- fp16 conversions ----------------
__global__ void k_cvtx(const float* __restrict__ x) {
    int i = blockIdx.x * blockDim.x + threadIdx.x;
    if (i >= NN * FIN / 8) return;
    const float4* p = (const float4*)x + (size_t)i * 2;
    float4 a = p[0], b = p[1];
    union { uint4 u; __half2 h[4]; } pk;
    pk.h[0] = __floats2half2_rn(a.x, a.y);
    pk.h[1] = __floats2half2_rn(a.z, a.w);
    pk.h[2] = __floats2half2_rn(b.x, b.y);
    pk.h[3] = __floats2half2_rn(b.z, b.w);
    ((uint4*)g_xh)[i] = pk.u;
}

__global__ void k_cvtw(const float* __restrict__ W1, const float* __restrict__ W2) {
    int i = blockIdx.x * blockDim.x + threadIdx.x;
    const int n1 = FIN * C1 / 8;   // 8192
    const int n2 = C1 * HID / 8;   // 4096
    if (i >= n1 + n2) return;
    const float* src; __half* dst; int j;
    if (i < n1) { src = W1; dst = g_w1h; j = i; }
    else        { src = W2; dst = g_w2h; j = i - n1; }
    const float4* p = (const float4*)src + (size_t)j * 2;
    float4 a = p[0], b = p[1];
    union { uint4 u; __half2 h[4]; } pk;
    pk.h[0] = __floats2half2_rn(a.x, a.y);
    pk.h[1] = __floats2half2_rn(a.z, a.w);
    pk.h[2] = __floats2half2_rn(b.x, b.y);
    pk.h[3] = __floats2half2_rn(b.z, b.w);
    ((uint4*)dst)[j] = pk.u;
}

// ---------------- GEMM1 (tensor core) + att scores -------------------------
// C[128,128] = Xh[128,128] @ W1h[128, bn..bn+128], K=128 fully resident.
// 8 warps as 2(m)x4(n), warp tile 64x32, m16n16k16 fragments.
__global__ void __launch_bounds__(256, 2)
k_gemm1(const float* __restrict__ att_s, const float* __restrict__ att_d) {
    extern __shared__ char dsm[];
    __half* As = (__half*)dsm;              // [128][136]
    __half* Bs = As + 128 * 136;            // [128][136]
    float*  Cs = (float*)dsm;               // [128][132] (overlays after compute)
    __shared__ float s_att[4][64];
    int tid = threadIdx.x;
    int bm = blockIdx.y * 128, bn = blockIdx.x * 128;

    {   // stage att vectors for this block's 2 heads
        int a = tid >> 6, j = tid & 63;
        int h = (bn >> 6) + (a & 1);
        s_att[a][j] = (a < 2) ? att_s[h * 64 + j] : att_d[h * 64 + j];
    }
    #pragma unroll
    for (int i = 0; i < 8; i++) {
        int idx = tid + i * 256;
        int r = idx >> 4, q = idx & 15;
        int gm = bm + r;
        uint4 v = (gm < NN) ? *(const uint4*)&g_xh[(size_t)gm * FIN + q * 8]
                            : make_uint4(0, 0, 0, 0);
        *(uint4*)&As[r * 136 + q * 8] = v;
    }
    #pragma unroll
    for (int i = 0; i < 8; i++) {
        int idx = tid + i * 256;
        int r = idx >> 4, q = idx & 15;
        *(uint4*)&Bs[r * 136 + q * 8] =
            *(const uint4*)&g_w1h[(size_t)r * C1 + bn + q * 8];
    }
    __syncthreads();

    int wid = tid >> 5;
    int wm = wid >> 2, wn = wid & 3;
    wmma::fragment<wmma::accumulator, 16, 16, 16, float> acc[4][2];
    #pragma unroll
    for (int i = 0; i < 4; i++)
        #pragma unroll
        for (int j = 0; j < 2; j++) wmma::fill_fragment(acc[i][j], 0.0f);

    #pragma unroll
    for (int kt = 0; kt < 8; kt++) {
        wmma::fragment<wmma::matrix_a, 16, 16, 16, __half, wmma::row_major> af[4];
        wmma::fragment<wmma::matrix_b, 16, 16, 16, __half, wmma::row_major> bf[2];
        #pragma unroll
        for (int i = 0; i < 4; i++)
            wmma::load_matrix_sync(af[i], As + (wm * 64 + i * 16) * 136 + kt * 16, 136);
        #pragma unroll
        for (int j = 0; j < 2; j++)
            wmma::load_matrix_sync(bf[j], Bs + (kt * 16) * 136 + wn * 32 + j * 16, 136);
        #pragma unroll
        for (int i = 0; i < 4; i++)
            #pragma unroll
            for (int j = 0; j < 2; j++)
                wmma::mma_sync(acc[i][j], af[i], bf[j], acc[i][j]);
    }
    __syncthreads();
    #pragma unroll
    for (int i = 0; i < 4; i++)
        #pragma unroll
        for (int j = 0; j < 2; j++)
            wmma::store_matrix_sync(Cs + (wm * 64 + i * 16) * 132 + wn * 32 + j * 16,
                                    acc[i][j], 132, wmma::mem_row_major);
    __syncthreads();

    // epilogue: fp16 store + att dots; thread = (row, col-half)
    int r = tid >> 1, half = tid & 1;
    int gm = bm + r;
    if (gm < NN) {
        int hglob = (bn >> 6) + half;
        const float* crow = Cs + r * 132 + half * 64;
        float sp = 0.f, dp = 0.f;
        #pragma unroll
        for (int q = 0; q < 8; q++) {
            float v[8];
            *(float4*)&v[0] = *(const float4*)&crow[q * 8];
            *(float4*)&v[4] = *(const float4*)&crow[q * 8 + 4];
            union { uint4 u; __half2 h[4]; } pk;
            pk.h[0] = __floats2half2_rn(v[0], v[1]);
            pk.h[1] = __floats2half2_rn(v[2], v[3]);
            pk.h[2] = __floats2half2_rn(v[4], v[5]);
            pk.h[3] = __floats2half2_rn(v[6], v[7]);
            *(uint4*)&g_h1h[(size_t)gm * C1 + bn + half * 64 + q * 8] = pk.u;
            #pragma unroll
            for (int jj = 0; jj < 8; jj++) {
                sp = fmaf(v[jj], s_att[half][q * 8 + jj], sp);
                dp = fmaf(v[jj], s_att[2 + half][q * 8 + jj], dp);
            }
        }
        g_as1[gm * H1 + hglob] = sp;
        g_ad1[gm * H1 + hglob] = dp;
    }
}

// ---------------- GEMM2 (tensor core) + att scores -------------------------
// C[128,64] = g_hah[128,512] @ W2h[512,64]; BK=64, double-buffered.
// 8 warps as 4(m)x2(n), warp tile 32x32.
__global__ void __launch_bounds__(256, 2)
k_gemm2(const float* __restrict__ att_s, const float* __restrict__ att_d) {
    extern __shared__ char dsm[];
    __half* Asb = (__half*)dsm;             // 2 x [128][72]
    __half* Bsb = Asb + 2 * 128 * 72;       // 2 x [64][72]
    float*  Cs  = (float*)dsm;              // [128][68] (overlay after compute)
    __shared__ float s_att[2][64];
    int tid = threadIdx.x;
    int bm = blockIdx.x * 128;

    if (tid < 128) {
        int a = tid >> 6, j = tid & 63;
        s_att[a][j] = a ? att_d[j] : att_s[j];
    }
    // preload k-tile 0
    #pragma unroll
    for (int i = 0; i < 4; i++) {
        int idx = tid + i * 256;
        int r = idx >> 3, q = idx & 7;
        int gm = bm + r;
        uint4 v = (gm < NN) ? *(const uint4*)&g_hah[(size_t)gm * C1 + q * 8]
                            : make_uint4(0, 0, 0, 0);
        *(uint4*)&Asb[r * 72 + q * 8] = v;
    }
    #pragma unroll
    for (int i = 0; i < 2; i++) {
        int idx = tid + i * 256;
        int r = idx >> 3, q = idx & 7;
        *(uint4*)&Bsb[r * 72 + q * 8] = *(const uint4*)&g_w2h[(size_t)r * HID + q * 8];
    }
    __syncthreads();

    int wid = tid >> 5;
    int wm = wid >> 1, wn = wid & 1;
    wmma::fragment<wmma::accumulator, 16, 16, 16, float> acc[2][2];
    #pragma unroll
    for (int i = 0; i < 2; i++)
        #pragma unroll
        for (int j = 0; j < 2; j++) wmma::fill_fragment(acc[i][j], 0.0f);

    for (int kt = 0; kt < 8; kt++) {
        int buf = kt & 1;
        uint4 pa[4], pb[2];
        if (kt < 7) {
            int k0 = (kt + 1) * 64;
            #pragma unroll
            for (int i = 0; i < 4; i++) {
                int idx = tid + i * 256;
                int r = idx >> 3, q = idx & 7;
                int gm = bm + r;
                pa[i] = (gm < NN) ? *(const uint4*)&g_hah[(size_t)gm * C1 + k0 + q * 8]
                                  : make_uint4(0, 0, 0, 0);
            }
            #pragma unroll
            for (int i = 0; i < 2; i++) {
                int idx = tid + i * 256;
                int r = idx >> 3, q = idx & 7;
                pb[i] = *(const uint4*)&g_w2h[(size_t)(k0 + r) * HID + q * 8];
            }
        }
        __half* As = Asb + buf * (128 * 72);
        __half* Bs = Bsb + buf * (64 * 72);
        #pragma unroll
        for (int ks = 0; ks < 4; ks++) {
            wmma::fragment<wmma::matrix_a, 16, 16, 16, __half, wmma::row_major> af[2];
            wmma::fragment<wmma::matrix_b, 16, 16, 16, __half, wmma::row_major> bf[2];
            #pragma unroll
            for (int i = 0; i < 2; i++)
                wmma::load_matrix_sync(af[i], As + (wm * 32 + i * 16) * 72 + ks * 16, 72);
            #pragma unroll
            for (int j = 0; j < 2; j++)
                wmma::load_matrix_sync(bf[j], Bs + (ks * 16) * 72 + wn * 32 + j * 16, 72);
            #pragma unroll
            for (int i = 0; i < 2; i++)
                #pragma unroll
                for (int j = 0; j < 2; j++)
                    wmma::mma_sync(acc[i][j], af[i], bf[j], acc[i][j]);
        }
        if (kt < 7) {
            int nb = buf ^ 1;
            __half* Asn = Asb + nb * (128 * 72);
            __half* Bsn = Bsb + nb * (64 * 72);
            #pragma unroll
            for (int i = 0; i < 4; i++) {
                int idx = tid + i * 256;
                int r = idx >> 3, q = idx & 7;
                *(uint4*)&Asn[r * 72 + q * 8] = pa[i];
            }
            #pragma unroll
            for (int i = 0; i < 2; i++) {
                int idx = tid + i * 256;
                int r = idx >> 3, q = idx & 7;
                *(uint4*)&Bsn[r * 72 + q * 8] = pb[i];
            }
            __syncthreads();
        }
    }
    __syncthreads();
    #pragma unroll
    for (int i = 0; i < 2; i++)
        #pragma unroll
        for (int j = 0; j < 2; j++)
            wmma::store_matrix_sync(Cs + (wm * 32 + i * 16) * 68 + wn * 32 + j * 16,
                                    acc[i][j], 68, wmma::mem_row_major);
    __syncthreads();

    // epilogue: fp16 store + single-head att dots (pairs of threads per row)
    int r = tid >> 1, half = tid & 1;
    int gm = bm + r;
    float sp = 0.f, dp = 0.f;
    if (gm < NN) {
        const float* crow = Cs + r * 68 + half * 32;
        #pragma unroll
        for (int q = 0; q < 4; q++) {
            float v[8];
            *(float4*)&v[0] = *(const float4*)&crow[q * 8];
            *(float4*)&v[4] = *(const float4*)&crow[q * 8 + 4];
            union { uint4 u; __half2 h[4]; } pk;
            pk.h[0] = __floats2half2_rn(v[0], v[1]);
            pk.h[1] = __floats2half2_rn(v[2], v[3]);
            pk.h[2] = __floats2half2_rn(v[4], v[5]);
            pk.h[3] = __floats2half2_rn(v[6], v[7]);
            *(uint4*)&g_h2h[(size_t)gm * HID + half * 32 + q * 8] = pk.u;
            #pragma unroll
            for (int jj = 0; jj < 8; jj++) {
                sp = fmaf(v[jj], s_att[0][half * 32 + q * 8 + jj], sp);
                dp = fmaf(v[jj], s_att[1][half * 32 + q * 8 + jj], dp);
            }
        }
    }
    sp += __shfl_xor_sync(0xffffffffu, sp, 1);
    dp += __shfl_xor_sync(0xffffffffu, dp, 1);
    if (gm < NN && half == 0) { g_as2[gm] = sp; g_ad2[gm] = dp; }
}

__device__ __forceinline__ float lrelu(float e) {
    return e > 0.f ? e : NEG_SLOPE * e;
}

// ---------------- gather1: one block per dst, warp h = head h --------------
__global__ void __launch_bounds__(256, 8)
k_gather1(const float* __restrict__ bias) {
    int d = blockIdx.x;
    int h = threadIdx.x >> 5, lane = threadIdx.x & 31;
    int r0 = g_rowptr[d], r1 = g_rowptr[d + 1];
    float ad = g_ad1[d * H1 + h];
    __shared__ int s_src[64];

    float den = 0.f, a0 = 0.f, a1 = 0.f;
    for (int base = r0; base < r1; base += 64) {
        int cl = min(64, r1 - base);
        __syncthreads();
        for (int i = threadIdx.x; i < cl; i += 256) s_src[i] = g_esrc[base + i];
        __syncthreads();
        for (int i = 0; i < cl; i++) {
            int s = s_src[i];
            float e = lrelu(__ldg(&g_as1[s * H1 + h]) + ad);
            float w = __expf(e);
            den += w;
            __half2 v = ((const __half2*)(g_h1h + (size_t)s * C1 + h * HID))[lane];
            float2 vf = __half22float2(v);
            a0 = fmaf(w, vf.x, a0);
            a1 = fmaf(w, vf.y, a1);
        }
    }
    float inv = 1.f / (den + EPS);
    int c0 = h * HID + 2 * lane;
    float o0 = a0 * inv + bias[c0];
    float o1 = a1 * inv + bias[c0 + 1];
    o0 = o0 > 0.f ? o0 : expm1f(o0);
    o1 = o1 > 0.f ? o1 : expm1f(o1);
    *(__half2*)&g_hah[(size_t)d * C1 + c0] = __floats2half2_rn(o0, o1);
}

// ---------------- gather2: one warp per dst --------------------------------
__global__ void k_gather2(const float* __restrict__ bias) {
    int d = (blockIdx.x * blockDim.x + threadIdx.x) >> 5;
    int lane = threadIdx.x & 31;
    if (d >= NN) return;
    float ad = g_ad2[d];
    int r0 = g_rowptr[d], r1 = g_rowptr[d + 1];

    float den = 0.f, a0 = 0.f, a1 = 0.f;
    for (int i = r0; i < r1; i++) {
        int s = __ldg(&g_esrc[i]);
        float e = lrelu(__ldg(&g_as2[s]) + ad);
        float w = __expf(e);
        den += w;
        __half2 v = ((const __half2*)(g_h2h + (size_t)s * HID))[lane];
        float2 vf = __half22float2(v);
        a0 = fmaf(w, vf.x, a0);
        a1 = fmaf(w, vf.y, a1);
    }
    float inv = 1.f / (den + EPS);
    int c0 = 2 * lane;
    g_out2[(size_t)d * HID + c0]     = a0 * inv + bias[c0];
    g_out2[(size_t)d * HID + c0 + 1] = a1 * inv + bias[c0 + 1];
}

// ---------------- global mean pool + final linear ----------------
__device__ __forceinline__ int lb32(const int* a, int n, int v) {
    int lo = 0, hi = n;
    while (lo < hi) { int mid = (lo + hi) >> 1; if (a[mid] < v) lo = mid + 1; else hi = mid; }
    return lo;
}

__global__ void k_pool(const int* __restrict__ batch,
                       const float* __restrict__ linW,
                       const float* __restrict__ linb,
                       float* __restrict__ out) {
    __shared__ float sm[256];
    int g = blockIdx.x;
    int lo = lb32(batch, NN, g);
    int hi = lb32(batch, NN, g + 1);
    int c = threadIdx.x & 63;
    int sub = threadIdx.x >> 6;
    float acc = 0.f;
    for (int n = lo + sub; n < hi; n += 4)
        acc += g_out2[(size_t)n * HID + c];
    sm[threadIdx.x] = acc;
    __syncthreads();
    if (threadIdx.x < 64) {
        float v = sm[threadIdx.x] + sm[threadIdx.x + 64] + sm[threadIdx.x + 128] + sm[threadIdx.x + 192];
        sm[threadIdx.x] = v * linW[threadIdx.x];
    }
    __syncthreads();
    if (threadIdx.x < 32) {
        float v = sm[threadIdx.x] + sm[threadIdx.x + 32];
        #pragma unroll
        for (int off = 16; off; off >>= 1) v += __shfl_down_sync(0xffffffffu, v, off);
        if (threadIdx.x == 0) {
            float cnt = (float)(hi - lo);
            out[g] = v / fmaxf(cnt, 1.f) + linb[0];
        }
    }
}

// ---------------- launch ----------------
extern "C" void kernel_launch(void* const* d_in, const int* in_sizes, int n_in,
                              void* d_out, int out_size) {
    const float* x     = (const float*)d_in[0];
    const int*   ei    = (const int*)d_in[1];
    const int*   batch = (const int*)d_in[2];
    const float* W1   = (const float*)d_in[3];
    const float* as1  = (const float*)d_in[4];
    const float* ad1  = (const float*)d_in[5];
    const float* b1   = (const float*)d_in[6];
    const float* W2   = (const float*)d_in[7];
    const float* as2  = (const float*)d_in[8];
    const float* ad2  = (const float*)d_in[9];
    const float* b2   = (const float*)d_in[10];
    const float* linW = (const float*)d_in[11];
    const float* linb = (const float*)d_in[12];
    float* out = (float*)d_out;
    (void)in_sizes; (void)n_in; (void)out_size;

    static bool attr_done = false;
    if (!attr_done) {
        cudaFuncSetAttribute(k_gemm1, cudaFuncAttributeMaxDynamicSharedMemorySize, 69632);
        cudaFuncSetAttribute(k_gemm2, cudaFuncAttributeMaxDynamicSharedMemorySize, 55296);
        attr_done = true;
    }

    // CSR build + fp16 conversions
    k_zero<<<(NN + 255) / 256, 256>>>();
    k_count<<<(ET + 255) / 256, 256>>>(ei);
    k_cvtx<<<(NN * FIN / 8 + 255) / 256, 256>>>(x);
    k_cvtw<<<(12288 + 255) / 256, 256>>>(W1, W2);
    k_scan<<<1, 1024>>>();
    k_scatter<<<(ET + 255) / 256, 256>>>(ei);
    k_sortseg<<<(NN + 255) / 256, 256>>>();

    // layer 1
    {
        dim3 grid(C1 / 128, (NN + 127) / 128);
        k_gemm1<<<grid, 256, 69632>>>(as1, ad1);
    }
    k_gather1<<<NN, 256>>>(b1);

    // layer 2
    k_gemm2<<<(NN + 127) / 128, 256, 55296>>>(as2, ad2);
    k_gather2<<<(NN + 7) / 8, 256>>>(b2);

    // pool + linear
    k_pool<<<GG, 256>>>(batch, linW, linb, out);
}

// round 10
// speedup vs baseline: 2.0286x; 1.1651x over previous
#include <cuda_runtime.h>
#include <cuda_fp16.h>
#include <mma.h>
#include <math.h>

using namespace nvcuda;

#define NN 50000
#define EE 800000
#define ET (EE + NN)
#define FIN 128
#define HID 64
#define H1 8
#define C1 (H1 * HID)   // 512
#define GG 64
#define NEG_SLOPE 0.2f
#define EPS 1e-16f
#define SCAN_B 1024
#define SCAN_NB ((NN + SCAN_B - 1) / SCAN_B)   // 49

// ---------------- scratch (device globals; no allocations allowed) ----------
__device__ __half g_xh[(size_t)NN * FIN];
__device__ __half g_w1h[FIN * C1];
__device__ __half g_w2h[C1 * HID];
__device__ __half g_h1h[(size_t)NN * C1];
__device__ __half g_hah[(size_t)NN * C1];
__device__ __half g_h2h[(size_t)NN * HID];
__device__ float  g_as1[NN * H1];
__device__ float  g_ad1[NN * H1];
__device__ float  g_as2[NN];
__device__ float  g_ad2[NN];
__device__ float  g_out2[NN * HID];
__device__ int    g_deg[NN];
__device__ int    g_fill[NN];
__device__ int    g_rowptr[NN + 1];
__device__ int    g_part[64];
__device__ int    g_esrc[ET];

// ---------------- fp16 conversions (+ fused zero) ----------------
__global__ void k_cvtx(const float* __restrict__ x) {
    int i = blockIdx.x * blockDim.x + threadIdx.x;
    if (i < NN) { g_deg[i] = 0; g_fill[i] = 0; }
    if (i >= NN * FIN / 8) return;
    const float4* p = (const float4*)x + (size_t)i * 2;
    float4 a = p[0], b = p[1];
    union { uint4 u; __half2 h[4]; } pk;
    pk.h[0] = __floats2half2_rn(a.x, a.y);
    pk.h[1] = __floats2half2_rn(a.z, a.w);
    pk.h[2] = __floats2half2_rn(b.x, b.y);
    pk.h[3] = __floats2half2_rn(b.z, b.w);
    ((uint4*)g_xh)[i] = pk.u;
}

__global__ void k_cvtw(const float* __restrict__ W1, const float* __restrict__ W2) {
    int i = blockIdx.x * blockDim.x + threadIdx.x;
    const int n1 = FIN * C1 / 8;
    const int n2 = C1 * HID / 8;
    if (i >= n1 + n2) return;
    const float* src; __half* dst; int j;
    if (i < n1) { src = W1; dst = g_w1h; j = i; }
    else        { src = W2; dst = g_w2h; j = i - n1; }
    const float4* p = (const float4*)src + (size_t)j * 2;
    float4 a = p[0], b = p[1];
    union { uint4 u; __half2 h[4]; } pk;
    pk.h[0] = __floats2half2_rn(a.x, a.y);
    pk.h[1] = __floats2half2_rn(a.z, a.w);
    pk.h[2] = __floats2half2_rn(b.x, b.y);
    pk.h[3] = __floats2half2_rn(b.z, b.w);
    ((uint4*)dst)[j] = pk.u;
}

// ---------------- CSR build ----------------
__global__ void k_count(const int* __restrict__ ei) {
    int i = blockIdx.x * blockDim.x + threadIdx.x;
    if (i >= ET) return;
    int dst = (i < EE) ? ei[EE + i] : (i - EE);
    atomicAdd(&g_deg[dst], 1);
}

// 3-phase exclusive scan of g_deg -> g_rowptr
__global__ void k_scan_a() {
    __shared__ int s[SCAN_B];
    int i = blockIdx.x * SCAN_B + threadIdx.x;
    int v = (i < NN) ? g_deg[i] : 0;
    s[threadIdx.x] = v;
    __syncthreads();
    #pragma unroll
    for (int off = 1; off < SCAN_B; off <<= 1) {
        int t = (threadIdx.x >= off) ? s[threadIdx.x - off] : 0;
        __syncthreads();
        s[threadIdx.x] += t;
        __syncthreads();
    }
    if (i < NN) g_rowptr[i] = s[threadIdx.x] - v;   // local exclusive
    if (threadIdx.x == SCAN_B - 1) g_part[blockIdx.x] = s[SCAN_B - 1];
}

// One warp (32 lanes), two-segment scan of g_part[0..SCAN_NB-1] (SCAN_NB<=64).
__global__ void k_scan_b() {
    int lane = threadIdx.x;                      // 0..31
    int v0 = (lane < SCAN_NB) ? g_part[lane] : 0;
    int v1 = (lane + 32 < SCAN_NB) ? g_part[lane + 32] : 0;
    int x0 = v0;
    #pragma unroll
    for (int off = 1; off < 32; off <<= 1) {
        int t = __shfl_up_sync(0xffffffffu, x0, off);
        if (lane >= off) x0 += t;
    }
    int total0 = __shfl_sync(0xffffffffu, x0, 31);
    int x1 = v1;
    #pragma unroll
    for (int off = 1; off < 32; off <<= 1) {
        int t = __shfl_up_sync(0xffffffffu, x1, off);
        if (lane >= off) x1 += t;
    }
    x1 += total0;
    if (lane < SCAN_NB) g_part[lane] = x0 - v0;
    if (lane + 32 < SCAN_NB) g_part[lane + 32] = x1 - v1;
    if (lane == 31) g_rowptr[NN] = x1;           // grand total (tail lanes add 0)
}

__global__ void k_scan_c() {
    int i = blockIdx.x * SCAN_B + threadIdx.x;
    if (i < NN) g_rowptr[i] += g_part[blockIdx.x];
}

__global__ void k_scatter(const int* __restrict__ ei) {
    int i = blockIdx.x * blockDim.x + threadIdx.x;
    if (i >= ET) return;
    int src, dst;
    if (i < EE) { src = ei[i]; dst = ei[EE + i]; }
    else        { src = i - EE; dst = i - EE; }
    int pos = g_rowptr[dst] + atomicAdd(&g_fill[dst], 1);
    g_esrc[pos] = src;
}

__global__ void k_sortseg() {
    int d = blockIdx.x * blockDim.x + threadIdx.x;
    if (d >= NN) return;
    int r0 = g_rowptr[d], r1 = g_rowptr[d + 1];
    int len = r1 - r0;
    if (len <= 1) return;
    if (len <= 64) {
        int buf[64];
        for (int i = 0; i < len; i++) buf[i] = g_esrc[r0 + i];
        for (int i = 1; i < len; i++) {
            int key = buf[i], j = i - 1;
            while (j >= 0 && buf[j] > key) { buf[j + 1] = buf[j]; j--; }
            buf[j + 1] = key;
        }
        for (int i = 0; i < len; i++) g_esrc[r0 + i] = buf[i];
    } else {
        for (int i = r0 + 1; i < r1; i++) {
            int key = g_esrc[i], j = i - 1;
            while (j >= r0 && g_esrc[j] > key) { g_esrc[j + 1] = g_esrc[j]; j--; }
            g_esrc[j + 1] = key;
        }
    }
}

// ---------------- GEMM1 (tensor core) + att scores -------------------------
__global__ void __launch_bounds__(256, 2)
k_gemm1(const float* __restrict__ att_s, const float* __restrict__ att_d) {
    extern __shared__ char dsm[];
    __half* As = (__half*)dsm;              // [128][136]
    __half* Bs = As + 128 * 136;            // [128][136]
    float*  Cs = (float*)dsm;               // [128][132] (overlay after compute)
    __shared__ float s_att[4][64];
    int tid = threadIdx.x;
    int bm = blockIdx.y * 128, bn = blockIdx.x * 128;

    {
        int a = tid >> 6, j = tid & 63;
        int h = (bn >> 6) + (a & 1);
        s_att[a][j] = (a < 2) ? att_s[h * 64 + j] : att_d[h * 64 + j];
    }
    #pragma unroll
    for (int i = 0; i < 8; i++) {
        int idx = tid + i * 256;
        int r = idx >> 4, q = idx & 15;
        int gm = bm + r;
        uint4 v = (gm < NN) ? *(const uint4*)&g_xh[(size_t)gm * FIN + q * 8]
                            : make_uint4(0, 0, 0, 0);
        *(uint4*)&As[r * 136 + q * 8] = v;
    }
    #pragma unroll
    for (int i = 0; i < 8; i++) {
        int idx = tid + i * 256;
        int r = idx >> 4, q = idx & 15;
        *(uint4*)&Bs[r * 136 + q * 8] =
            *(const uint4*)&g_w1h[(size_t)r * C1 + bn + q * 8];
    }
    __syncthreads();

    int wid = tid >> 5;
    int wm = wid >> 2, wn = wid & 3;
    wmma::fragment<wmma::accumulator, 16, 16, 16, float> acc[4][2];
    #pragma unroll
    for (int i = 0; i < 4; i++)
        #pragma unroll
        for (int j = 0; j < 2; j++) wmma::fill_fragment(acc[i][j], 0.0f);

    #pragma unroll
    for (int kt = 0; kt < 8; kt++) {
        wmma::fragment<wmma::matrix_a, 16, 16, 16, __half, wmma::row_major> af[4];
        wmma::fragment<wmma::matrix_b, 16, 16, 16, __half, wmma::row_major> bf[2];
        #pragma unroll
        for (int i = 0; i < 4; i++)
            wmma::load_matrix_sync(af[i], As + (wm * 64 + i * 16) * 136 + kt * 16, 136);
        #pragma unroll
        for (int j = 0; j < 2; j++)
            wmma::load_matrix_sync(bf[j], Bs + (kt * 16) * 136 + wn * 32 + j * 16, 136);
        #pragma unroll
        for (int i = 0; i < 4; i++)
            #pragma unroll
            for (int j = 0; j < 2; j++)
                wmma::mma_sync(acc[i][j], af[i], bf[j], acc[i][j]);
    }
    __syncthreads();
    #pragma unroll
    for (int i = 0; i < 4; i++)
        #pragma unroll
        for (int j = 0; j < 2; j++)
            wmma::store_matrix_sync(Cs + (wm * 64 + i * 16) * 132 + wn * 32 + j * 16,
                                    acc[i][j], 132, wmma::mem_row_major);
    __syncthreads();

    int r = tid >> 1, half = tid & 1;
    int gm = bm + r;
    if (gm < NN) {
        int hglob = (bn >> 6) + half;
        const float* crow = Cs + r * 132 + half * 64;
        float sp = 0.f, dp = 0.f;
        #pragma unroll
        for (int q = 0; q < 8; q++) {
            float v[8];
            *(float4*)&v[0] = *(const float4*)&crow[q * 8];
            *(float4*)&v[4] = *(const float4*)&crow[q * 8 + 4];
            union { uint4 u; __half2 h[4]; } pk;
            pk.h[0] = __floats2half2_rn(v[0], v[1]);
            pk.h[1] = __floats2half2_rn(v[2], v[3]);
            pk.h[2] = __floats2half2_rn(v[4], v[5]);
            pk.h[3] = __floats2half2_rn(v[6], v[7]);
            *(uint4*)&g_h1h[(size_t)gm * C1 + bn + half * 64 + q * 8] = pk.u;
            #pragma unroll
            for (int jj = 0; jj < 8; jj++) {
                sp = fmaf(v[jj], s_att[half][q * 8 + jj], sp);
                dp = fmaf(v[jj], s_att[2 + half][q * 8 + jj], dp);
            }
        }
        g_as1[gm * H1 + hglob] = sp;
        g_ad1[gm * H1 + hglob] = dp;
    }
}

// ---------------- GEMM2 (tensor core) + att scores -------------------------
__global__ void __launch_bounds__(256, 2)
k_gemm2(const float* __restrict__ att_s, const float* __restrict__ att_d) {
    extern __shared__ char dsm[];
    __half* Asb = (__half*)dsm;             // 2 x [128][72]
    __half* Bsb = Asb + 2 * 128 * 72;       // 2 x [64][72]
    float*  Cs  = (float*)dsm;              // [128][68]
    __shared__ float s_att[2][64];
    int tid = threadIdx.x;
    int bm = blockIdx.x * 128;

    if (tid < 128) {
        int a = tid >> 6, j = tid & 63;
        s_att[a][j] = a ? att_d[j] : att_s[j];
    }
    #pragma unroll
    for (int i = 0; i < 4; i++) {
        int idx = tid + i * 256;
        int r = idx >> 3, q = idx & 7;
        int gm = bm + r;
        uint4 v = (gm < NN) ? *(const uint4*)&g_hah[(size_t)gm * C1 + q * 8]
                            : make_uint4(0, 0, 0, 0);
        *(uint4*)&Asb[r * 72 + q * 8] = v;
    }
    #pragma unroll
    for (int i = 0; i < 2; i++) {
        int idx = tid + i * 256;
        int r = idx >> 3, q = idx & 7;
        *(uint4*)&Bsb[r * 72 + q * 8] = *(const uint4*)&g_w2h[(size_t)r * HID + q * 8];
    }
    __syncthreads();

    int wid = tid >> 5;
    int wm = wid >> 1, wn = wid & 1;
    wmma::fragment<wmma::accumulator, 16, 16, 16, float> acc[2][2];
    #pragma unroll
    for (int i = 0; i < 2; i++)
        #pragma unroll
        for (int j = 0; j < 2; j++) wmma::fill_fragment(acc[i][j], 0.0f);

    for (int kt = 0; kt < 8; kt++) {
        int buf = kt & 1;
        uint4 pa[4], pb[2];
        if (kt < 7) {
            int k0 = (kt + 1) * 64;
            #pragma unroll
            for (int i = 0; i < 4; i++) {
                int idx = tid + i * 256;
                int r = idx >> 3, q = idx & 7;
                int gm = bm + r;
                pa[i] = (gm < NN) ? *(const uint4*)&g_hah[(size_t)gm * C1 + k0 + q * 8]
                                  : make_uint4(0, 0, 0, 0);
            }
            #pragma unroll
            for (int i = 0; i < 2; i++) {
                int idx = tid + i * 256;
                int r = idx >> 3, q = idx & 7;
                pb[i] = *(const uint4*)&g_w2h[(size_t)(k0 + r) * HID + q * 8];
            }
        }
        __half* As = Asb + buf * (128 * 72);
        __half* Bs = Bsb + buf * (64 * 72);
        #pragma unroll
        for (int ks = 0; ks < 4; ks++) {
            wmma::fragment<wmma::matrix_a, 16, 16, 16, __half, wmma::row_major> af[2];
            wmma::fragment<wmma::matrix_b, 16, 16, 16, __half, wmma::row_major> bf[2];
            #pragma unroll
            for (int i = 0; i < 2; i++)
                wmma::load_matrix_sync(af[i], As + (wm * 32 + i * 16) * 72 + ks * 16, 72);
            #pragma unroll
            for (int j = 0; j < 2; j++)
                wmma::load_matrix_sync(bf[j], Bs + (ks * 16) * 72 + wn * 32 + j * 16, 72);
            #pragma unroll
            for (int i = 0; i < 2; i++)
                #pragma unroll
                for (int j = 0; j < 2; j++)
                    wmma::mma_sync(acc[i][j], af[i], bf[j], acc[i][j]);
        }
        if (kt < 7) {
            int nb = buf ^ 1;
            __half* Asn = Asb + nb * (128 * 72);
            __half* Bsn = Bsb + nb * (64 * 72);
            #pragma unroll
            for (int i = 0; i < 4; i++) {
                int idx = tid + i * 256;
                int r = idx >> 3, q = idx & 7;
                *(uint4*)&Asn[r * 72 + q * 8] = pa[i];
            }
            #pragma unroll
            for (int i = 0; i < 2; i++) {
                int idx = tid + i * 256;
                int r = idx >> 3, q = idx & 7;
                *(uint4*)&Bsn[r * 72 + q * 8] = pb[i];
            }
            __syncthreads();
        }
    }
    __syncthreads();
    #pragma unroll
    for (int i = 0; i < 2; i++)
        #pragma unroll
        for (int j = 0; j < 2; j++)
            wmma::store_matrix_sync(Cs + (wm * 32 + i * 16) * 68 + wn * 32 + j * 16,
                                    acc[i][j], 68, wmma::mem_row_major);
    __syncthreads();

    int r = tid >> 1, half = tid & 1;
    int gm = bm + r;
    float sp = 0.f, dp = 0.f;
    if (gm < NN) {
        const float* crow = Cs + r * 68 + half * 32;
        #pragma unroll
        for (int q = 0; q < 4; q++) {
            float v[8];
            *(float4*)&v[0] = *(const float4*)&crow[q * 8];
            *(float4*)&v[4] = *(const float4*)&crow[q * 8 + 4];
            union { uint4 u; __half2 h[4]; } pk;
            pk.h[0] = __floats2half2_rn(v[0], v[1]);
            pk.h[1] = __floats2half2_rn(v[2], v[3]);
            pk.h[2] = __floats2half2_rn(v[4], v[5]);
            pk.h[3] = __floats2half2_rn(v[6], v[7]);
            *(uint4*)&g_h2h[(size_t)gm * HID + half * 32 + q * 8] = pk.u;
            #pragma unroll
            for (int jj = 0; jj < 8; jj++) {
                sp = fmaf(v[jj], s_att[0][half * 32 + q * 8 + jj], sp);
                dp = fmaf(v[jj], s_att[1][half * 32 + q * 8 + jj], dp);
            }
        }
    }
    sp += __shfl_xor_sync(0xffffffffu, sp, 1);
    dp += __shfl_xor_sync(0xffffffffu, dp, 1);
    if (gm < NN && half == 0) { g_as2[gm] = sp; g_ad2[gm] = dp; }
}

__device__ __forceinline__ float lrelu(float e) {
    return e > 0.f ? e : NEG_SLOPE * e;
}

// ---------------- gather1: block per dst, warp h = head h ------------------
__global__ void __launch_bounds__(256, 8)
k_gather1(const float* __restrict__ bias) {
    int d = blockIdx.x;
    int h = threadIdx.x >> 5, lane = threadIdx.x & 31;
    int r0 = g_rowptr[d], r1 = g_rowptr[d + 1];
    float ad = g_ad1[d * H1 + h];

    float den = 0.f, a0 = 0.f, a1 = 0.f;
    for (int base = r0; base < r1; base += 32) {
        int n = min(32, r1 - base);
        int sv = (base + lane < r1) ? __ldg(&g_esrc[base + lane]) : 0;
        #pragma unroll 4
        for (int j = 0; j < n; j++) {
            int s = __shfl_sync(0xffffffffu, sv, j);
            float e = lrelu(__ldg(&g_as1[s * H1 + h]) + ad);
            float w = __expf(e);
            den += w;
            __half2 v = ((const __half2*)(g_h1h + (size_t)s * C1 + h * HID))[lane];
            float2 vf = __half22float2(v);
            a0 = fmaf(w, vf.x, a0);
            a1 = fmaf(w, vf.y, a1);
        }
    }
    float inv = 1.f / (den + EPS);
    int c0 = h * HID + 2 * lane;
    float o0 = a0 * inv + bias[c0];
    float o1 = a1 * inv + bias[c0 + 1];
    o0 = o0 > 0.f ? o0 : expm1f(o0);
    o1 = o1 > 0.f ? o1 : expm1f(o1);
    *(__half2*)&g_hah[(size_t)d * C1 + c0] = __floats2half2_rn(o0, o1);
}

// ---------------- gather2: warp per dst ------------------------------------
__global__ void __launch_bounds__(256, 8)
k_gather2(const float* __restrict__ bias) {
    int d = (blockIdx.x * blockDim.x + threadIdx.x) >> 5;
    int lane = threadIdx.x & 31;
    if (d >= NN) return;
    float ad = g_ad2[d];
    int r0 = g_rowptr[d], r1 = g_rowptr[d + 1];

    float den = 0.f, a0 = 0.f, a1 = 0.f;
    for (int base = r0; base < r1; base += 32) {
        int n = min(32, r1 - base);
        int sv = (base + lane < r1) ? __ldg(&g_esrc[base + lane]) : 0;
        #pragma unroll 4
        for (int j = 0; j < n; j++) {
            int s = __shfl_sync(0xffffffffu, sv, j);
            float e = lrelu(__ldg(&g_as2[s]) + ad);
            float w = __expf(e);
            den += w;
            __half2 v = ((const __half2*)(g_h2h + (size_t)s * HID))[lane];
            float2 vf = __half22float2(v);
            a0 = fmaf(w, vf.x, a0);
            a1 = fmaf(w, vf.y, a1);
        }
    }
    float inv = 1.f / (den + EPS);
    int c0 = 2 * lane;
    g_out2[(size_t)d * HID + c0]     = a0 * inv + bias[c0];
    g_out2[(size_t)d * HID + c0 + 1] = a1 * inv + bias[c0 + 1];
}

// ---------------- global mean pool + final linear ----------------
__device__ __forceinline__ int lb32(const int* a, int n, int v) {
    int lo = 0, hi = n;
    while (lo < hi) { int mid = (lo + hi) >> 1; if (a[mid] < v) lo = mid + 1; else hi = mid; }
    return lo;
}

__global__ void k_pool(const int* __restrict__ batch,
                       const float* __restrict__ linW,
                       const float* __restrict__ linb,
                       float* __restrict__ out) {
    __shared__ float sm[256];
    int g = blockIdx.x;
    int lo = lb32(batch, NN, g);
    int hi = lb32(batch, NN, g + 1);
    int c = threadIdx.x & 63;
    int sub = threadIdx.x >> 6;
    float acc = 0.f;
    for (int n = lo + sub; n < hi; n += 4)
        acc += g_out2[(size_t)n * HID + c];
    sm[threadIdx.x] = acc;
    __syncthreads();
    if (threadIdx.x < 64) {
        float v = sm[threadIdx.x] + sm[threadIdx.x + 64] + sm[threadIdx.x + 128] + sm[threadIdx.x + 192];
        sm[threadIdx.x] = v * linW[threadIdx.x];
    }
    __syncthreads();
    if (threadIdx.x < 32) {
        float v = sm[threadIdx.x] + sm[threadIdx.x + 32];
        #pragma unroll
        for (int off = 16; off; off >>= 1) v += __shfl_down_sync(0xffffffffu, v, off);
        if (threadIdx.x == 0) {
            float cnt = (float)(hi - lo);
            out[g] = v / fmaxf(cnt, 1.f) + linb[0];
        }
    }
}

// ---------------- launch ----------------
extern "C" void kernel_launch(void* const* d_in, const int* in_sizes, int n_in,
                              void* d_out, int out_size) {
    const float* x     = (const float*)d_in[0];
    const int*   ei    = (const int*)d_in[1];
    const int*   batch = (const int*)d_in[2];
    const float* W1   = (const float*)d_in[3];
    const float* as1  = (const float*)d_in[4];
    const float* ad1  = (const float*)d_in[5];
    const float* b1   = (const float*)d_in[6];
    const float* W2   = (const float*)d_in[7];
    const float* as2  = (const float*)d_in[8];
    const float* ad2  = (const float*)d_in[9];
    const float* b2   = (const float*)d_in[10];
    const float* linW = (const float*)d_in[11];
    const float* linb = (const float*)d_in[12];
    float* out = (float*)d_out;
    (void)in_sizes; (void)n_in; (void)out_size;

    cudaFuncSetAttribute(k_gemm1, cudaFuncAttributeMaxDynamicSharedMemorySize, 69632);
    cudaFuncSetAttribute(k_gemm2, cudaFuncAttributeMaxDynamicSharedMemorySize, 55296);

    // conversions (+zero) and CSR build
    k_cvtx<<<(NN * FIN / 8 + 255) / 256, 256>>>(x);
    k_cvtw<<<(12288 + 255) / 256, 256>>>(W1, W2);
    k_count<<<(ET + 255) / 256, 256>>>(ei);
    k_scan_a<<<SCAN_NB, SCAN_B>>>();
    k_scan_b<<<1, 32>>>();
    k_scan_c<<<SCAN_NB, SCAN_B>>>();
    k_scatter<<<(ET + 255) / 256, 256>>>(ei);
    k_sortseg<<<(NN + 255) / 256, 256>>>();

    // layer 1
    {
        dim3 grid(C1 / 128, (NN + 127) / 128);
        k_gemm1<<<grid, 256, 69632>>>(as1, ad1);
    }
    k_gather1<<<NN, 256>>>(b1);

    // layer 2
    k_gemm2<<<(NN + 127) / 128, 256, 55296>>>(as2, ad2);
    k_gather2<<<(NN + 7) / 8, 256>>>(b2);

    // pool + linear
    k_pool<<<GG, 256>>>(batch, linW, linb, out);
}

// round 11
// speedup vs baseline: 2.2521x; 1.1102x over previous
#include <cuda_runtime.h>
#include <cuda_fp16.h>
#include <mma.h>
#include <math.h>

using namespace nvcuda;

#define NN 50000
#define EE 800000
#define ET (EE + NN)
#define FIN 128
#define HID 64
#define H1 8
#define C1 (H1 * HID)   // 512
#define GG 64
#define NEG_SLOPE 0.2f
#define EPS 1e-16f
#define SCAN_B 1024
#define SCAN_NB ((NN + SCAN_B - 1) / SCAN_B)   // 49

// ---------------- scratch (device globals; no allocations allowed) ----------
__device__ __half g_xh[(size_t)NN * FIN];
__device__ __half g_w1h[FIN * C1];
__device__ __half g_w2h[C1 * HID];
__device__ __half g_h1h[(size_t)NN * C1];
__device__ __half g_hah[(size_t)NN * C1];
__device__ __half g_h2h[(size_t)NN * HID];
__device__ float  g_as1[NN * H1];
__device__ float  g_ad1[NN * H1];
__device__ float  g_as2[NN];
__device__ float  g_ad2[NN];
__device__ float  g_out2[NN * HID];
__device__ int    g_deg[NN];
__device__ int    g_fill[NN];
__device__ int    g_rowptr[NN + 1];
__device__ int    g_part[64];
__device__ int    g_esrc[ET];

// ---------------- fp16 conversions (+ fused zero) ----------------
__global__ void k_cvtx(const float* __restrict__ x) {
    int i = blockIdx.x * blockDim.x + threadIdx.x;
    if (i < NN) { g_deg[i] = 0; g_fill[i] = 0; }
    if (i >= NN * FIN / 8) return;
    const float4* p = (const float4*)x + (size_t)i * 2;
    float4 a = p[0], b = p[1];
    union { uint4 u; __half2 h[4]; } pk;
    pk.h[0] = __floats2half2_rn(a.x, a.y);
    pk.h[1] = __floats2half2_rn(a.z, a.w);
    pk.h[2] = __floats2half2_rn(b.x, b.y);
    pk.h[3] = __floats2half2_rn(b.z, b.w);
    ((uint4*)g_xh)[i] = pk.u;
}

__global__ void k_cvtw(const float* __restrict__ W1, const float* __restrict__ W2) {
    int i = blockIdx.x * blockDim.x + threadIdx.x;
    const int n1 = FIN * C1 / 8;
    const int n2 = C1 * HID / 8;
    if (i >= n1 + n2) return;
    const float* src; __half* dst; int j;
    if (i < n1) { src = W1; dst = g_w1h; j = i; }
    else        { src = W2; dst = g_w2h; j = i - n1; }
    const float4* p = (const float4*)src + (size_t)j * 2;
    float4 a = p[0], b = p[1];
    union { uint4 u; __half2 h[4]; } pk;
    pk.h[0] = __floats2half2_rn(a.x, a.y);
    pk.h[1] = __floats2half2_rn(a.z, a.w);
    pk.h[2] = __floats2half2_rn(b.x, b.y);
    pk.h[3] = __floats2half2_rn(b.z, b.w);
    ((uint4*)dst)[j] = pk.u;
}

// ---------------- CSR build ----------------
__global__ void k_count(const int* __restrict__ ei) {
    int i = blockIdx.x * blockDim.x + threadIdx.x;
    if (i >= ET) return;
    int dst = (i < EE) ? ei[EE + i] : (i - EE);
    atomicAdd(&g_deg[dst], 1);
}

// 3-phase exclusive scan of g_deg -> g_rowptr
__global__ void k_scan_a() {
    __shared__ int s[SCAN_B];
    int i = blockIdx.x * SCAN_B + threadIdx.x;
    int v = (i < NN) ? g_deg[i] : 0;
    s[threadIdx.x] = v;
    __syncthreads();
    #pragma unroll
    for (int off = 1; off < SCAN_B; off <<= 1) {
        int t = (threadIdx.x >= off) ? s[threadIdx.x - off] : 0;
        __syncthreads();
        s[threadIdx.x] += t;
        __syncthreads();
    }
    if (i < NN) g_rowptr[i] = s[threadIdx.x] - v;   // local exclusive
    if (threadIdx.x == SCAN_B - 1) g_part[blockIdx.x] = s[SCAN_B - 1];
}

// One warp (32 lanes), two-segment scan of g_part[0..SCAN_NB-1] (SCAN_NB<=64).
__global__ void k_scan_b() {
    int lane = threadIdx.x;                      // 0..31
    int v0 = (lane < SCAN_NB) ? g_part[lane] : 0;
    int v1 = (lane + 32 < SCAN_NB) ? g_part[lane + 32] : 0;
    int x0 = v0;
    #pragma unroll
    for (int off = 1; off < 32; off <<= 1) {
        int t = __shfl_up_sync(0xffffffffu, x0, off);
        if (lane >= off) x0 += t;
    }
    int total0 = __shfl_sync(0xffffffffu, x0, 31);
    int x1 = v1;
    #pragma unroll
    for (int off = 1; off < 32; off <<= 1) {
        int t = __shfl_up_sync(0xffffffffu, x1, off);
        if (lane >= off) x1 += t;
    }
    x1 += total0;
    if (lane < SCAN_NB) g_part[lane] = x0 - v0;
    if (lane + 32 < SCAN_NB) g_part[lane + 32] = x1 - v1;
    if (lane == 31) g_rowptr[NN] = x1;
}

__global__ void k_scan_c() {
    int i = blockIdx.x * SCAN_B + threadIdx.x;
    if (i < NN) g_rowptr[i] += g_part[blockIdx.x];
}

__global__ void k_scatter(const int* __restrict__ ei) {
    int i = blockIdx.x * blockDim.x + threadIdx.x;
    if (i >= ET) return;
    int src, dst;
    if (i < EE) { src = ei[i]; dst = ei[EE + i]; }
    else        { src = i - EE; dst = i - EE; }
    int pos = g_rowptr[dst] + atomicAdd(&g_fill[dst], 1);
    g_esrc[pos] = src;
}

__global__ void k_sortseg() {
    int d = blockIdx.x * blockDim.x + threadIdx.x;
    if (d >= NN) return;
    int r0 = g_rowptr[d], r1 = g_rowptr[d + 1];
    int len = r1 - r0;
    if (len <= 1) return;
    if (len <= 64) {
        int buf[64];
        for (int i = 0; i < len; i++) buf[i] = g_esrc[r0 + i];
        for (int i = 1; i < len; i++) {
            int key = buf[i], j = i - 1;
            while (j >= 0 && buf[j] > key) { buf[j + 1] = buf[j]; j--; }
            buf[j + 1] = key;
        }
        for (int i = 0; i < len; i++) g_esrc[r0 + i] = buf[i];
    } else {
        for (int i = r0 + 1; i < r1; i++) {
            int key = g_esrc[i], j = i - 1;
            while (j >= r0 && g_esrc[j] > key) { g_esrc[j + 1] = g_esrc[j]; j--; }
            g_esrc[j + 1] = key;
        }
    }
}

// ---------------- GEMM1 (tensor core) + att scores -------------------------
__global__ void __launch_bounds__(256, 2)
k_gemm1(const float* __restrict__ att_s, const float* __restrict__ att_d) {
    extern __shared__ char dsm[];
    __half* As = (__half*)dsm;              // [128][136]
    __half* Bs = As + 128 * 136;            // [128][136]
    float*  Cs = (float*)dsm;               // [128][132] (overlay after compute)
    __shared__ float s_att[4][64];
    int tid = threadIdx.x;
    int bm = blockIdx.y * 128, bn = blockIdx.x * 128;

    {
        int a = tid >> 6, j = tid & 63;
        int h = (bn >> 6) + (a & 1);
        s_att[a][j] = (a < 2) ? att_s[h * 64 + j] : att_d[h * 64 + j];
    }
    #pragma unroll
    for (int i = 0; i < 8; i++) {
        int idx = tid + i * 256;
        int r = idx >> 4, q = idx & 15;
        int gm = bm + r;
        uint4 v = (gm < NN) ? *(const uint4*)&g_xh[(size_t)gm * FIN + q * 8]
                            : make_uint4(0, 0, 0, 0);
        *(uint4*)&As[r * 136 + q * 8] = v;
    }
    #pragma unroll
    for (int i = 0; i < 8; i++) {
        int idx = tid + i * 256;
        int r = idx >> 4, q = idx & 15;
        *(uint4*)&Bs[r * 136 + q * 8] =
            *(const uint4*)&g_w1h[(size_t)r * C1 + bn + q * 8];
    }
    __syncthreads();

    int wid = tid >> 5;
    int wm = wid >> 2, wn = wid & 3;
    wmma::fragment<wmma::accumulator, 16, 16, 16, float> acc[4][2];
    #pragma unroll
    for (int i = 0; i < 4; i++)
        #pragma unroll
        for (int j = 0; j < 2; j++) wmma::fill_fragment(acc[i][j], 0.0f);

    #pragma unroll
    for (int kt = 0; kt < 8; kt++) {
        wmma::fragment<wmma::matrix_a, 16, 16, 16, __half, wmma::row_major> af[4];
        wmma::fragment<wmma::matrix_b, 16, 16, 16, __half, wmma::row_major> bf[2];
        #pragma unroll
        for (int i = 0; i < 4; i++)
            wmma::load_matrix_sync(af[i], As + (wm * 64 + i * 16) * 136 + kt * 16, 136);
        #pragma unroll
        for (int j = 0; j < 2; j++)
            wmma::load_matrix_sync(bf[j], Bs + (kt * 16) * 136 + wn * 32 + j * 16, 136);
        #pragma unroll
        for (int i = 0; i < 4; i++)
            #pragma unroll
            for (int j = 0; j < 2; j++)
                wmma::mma_sync(acc[i][j], af[i], bf[j], acc[i][j]);
    }
    __syncthreads();
    #pragma unroll
    for (int i = 0; i < 4; i++)
        #pragma unroll
        for (int j = 0; j < 2; j++)
            wmma::store_matrix_sync(Cs + (wm * 64 + i * 16) * 132 + wn * 32 + j * 16,
                                    acc[i][j], 132, wmma::mem_row_major);
    __syncthreads();

    int r = tid >> 1, half = tid & 1;
    int gm = bm + r;
    if (gm < NN) {
        int hglob = (bn >> 6) + half;
        const float* crow = Cs + r * 132 + half * 64;
        float sp = 0.f, dp = 0.f;
        #pragma unroll
        for (int q = 0; q < 8; q++) {
            float v[8];
            *(float4*)&v[0] = *(const float4*)&crow[q * 8];
            *(float4*)&v[4] = *(const float4*)&crow[q * 8 + 4];
            union { uint4 u; __half2 h[4]; } pk;
            pk.h[0] = __floats2half2_rn(v[0], v[1]);
            pk.h[1] = __floats2half2_rn(v[2], v[3]);
            pk.h[2] = __floats2half2_rn(v[4], v[5]);
            pk.h[3] = __floats2half2_rn(v[6], v[7]);
            *(uint4*)&g_h1h[(size_t)gm * C1 + bn + half * 64 + q * 8] = pk.u;
            #pragma unroll
            for (int jj = 0; jj < 8; jj++) {
                sp = fmaf(v[jj], s_att[half][q * 8 + jj], sp);
                dp = fmaf(v[jj], s_att[2 + half][q * 8 + jj], dp);
            }
        }
        g_as1[gm * H1 + hglob] = sp;
        g_ad1[gm * H1 + hglob] = dp;
    }
}

// ---------------- GEMM2 (tensor core) + att scores -------------------------
__global__ void __launch_bounds__(256, 2)
k_gemm2(const float* __restrict__ att_s, const float* __restrict__ att_d) {
    extern __shared__ char dsm[];
    __half* Asb = (__half*)dsm;             // 2 x [128][72]
    __half* Bsb = Asb + 2 * 128 * 72;       // 2 x [64][72]
    float*  Cs  = (float*)dsm;              // [128][68]
    __shared__ float s_att[2][64];
    int tid = threadIdx.x;
    int bm = blockIdx.x * 128;

    if (tid < 128) {
        int a = tid >> 6, j = tid & 63;
        s_att[a][j] = a ? att_d[j] : att_s[j];
    }
    #pragma unroll
    for (int i = 0; i < 4; i++) {
        int idx = tid + i * 256;
        int r = idx >> 3, q = idx & 7;
        int gm = bm + r;
        uint4 v = (gm < NN) ? *(const uint4*)&g_hah[(size_t)gm * C1 + q * 8]
                            : make_uint4(0, 0, 0, 0);
        *(uint4*)&Asb[r * 72 + q * 8] = v;
    }
    #pragma unroll
    for (int i = 0; i < 2; i++) {
        int idx = tid + i * 256;
        int r = idx >> 3, q = idx & 7;
        *(uint4*)&Bsb[r * 72 + q * 8] = *(const uint4*)&g_w2h[(size_t)r * HID + q * 8];
    }
    __syncthreads();

    int wid = tid >> 5;
    int wm = wid >> 1, wn = wid & 1;
    wmma::fragment<wmma::accumulator, 16, 16, 16, float> acc[2][2];
    #pragma unroll
    for (int i = 0; i < 2; i++)
        #pragma unroll
        for (int j = 0; j < 2; j++) wmma::fill_fragment(acc[i][j], 0.0f);

    for (int kt = 0; kt < 8; kt++) {
        int buf = kt & 1;
        uint4 pa[4], pb[2];
        if (kt < 7) {
            int k0 = (kt + 1) * 64;
            #pragma unroll
            for (int i = 0; i < 4; i++) {
                int idx = tid + i * 256;
                int r = idx >> 3, q = idx & 7;
                int gm = bm + r;
                pa[i] = (gm < NN) ? *(const uint4*)&g_hah[(size_t)gm * C1 + k0 + q * 8]
                                  : make_uint4(0, 0, 0, 0);
            }
            #pragma unroll
            for (int i = 0; i < 2; i++) {
                int idx = tid + i * 256;
                int r = idx >> 3, q = idx & 7;
                pb[i] = *(const uint4*)&g_w2h[(size_t)(k0 + r) * HID + q * 8];
            }
        }
        __half* As = Asb + buf * (128 * 72);
        __half* Bs = Bsb + buf * (64 * 72);
        #pragma unroll
        for (int ks = 0; ks < 4; ks++) {
            wmma::fragment<wmma::matrix_a, 16, 16, 16, __half, wmma::row_major> af[2];
            wmma::fragment<wmma::matrix_b, 16, 16, 16, __half, wmma::row_major> bf[2];
            #pragma unroll
            for (int i = 0; i < 2; i++)
                wmma::load_matrix_sync(af[i], As + (wm * 32 + i * 16) * 72 + ks * 16, 72);
            #pragma unroll
            for (int j = 0; j < 2; j++)
                wmma::load_matrix_sync(bf[j], Bs + (ks * 16) * 72 + wn * 32 + j * 16, 72);
            #pragma unroll
            for (int i = 0; i < 2; i++)
                #pragma unroll
                for (int j = 0; j < 2; j++)
                    wmma::mma_sync(acc[i][j], af[i], bf[j], acc[i][j]);
        }
        if (kt < 7) {
            int nb = buf ^ 1;
            __half* Asn = Asb + nb * (128 * 72);
            __half* Bsn = Bsb + nb * (64 * 72);
            #pragma unroll
            for (int i = 0; i < 4; i++) {
                int idx = tid + i * 256;
                int r = idx >> 3, q = idx & 7;
                *(uint4*)&Asn[r * 72 + q * 8] = pa[i];
            }
            #pragma unroll
            for (int i = 0; i < 2; i++) {
                int idx = tid + i * 256;
                int r = idx >> 3, q = idx & 7;
                *(uint4*)&Bsn[r * 72 + q * 8] = pb[i];
            }
            __syncthreads();
        }
    }
    __syncthreads();
    #pragma unroll
    for (int i = 0; i < 2; i++)
        #pragma unroll
        for (int j = 0; j < 2; j++)
            wmma::store_matrix_sync(Cs + (wm * 32 + i * 16) * 68 + wn * 32 + j * 16,
                                    acc[i][j], 68, wmma::mem_row_major);
    __syncthreads();

    int r = tid >> 1, half = tid & 1;
    int gm = bm + r;
    float sp = 0.f, dp = 0.f;
    if (gm < NN) {
        const float* crow = Cs + r * 68 + half * 32;
        #pragma unroll
        for (int q = 0; q < 4; q++) {
            float v[8];
            *(float4*)&v[0] = *(const float4*)&crow[q * 8];
            *(float4*)&v[4] = *(const float4*)&crow[q * 8 + 4];
            union { uint4 u; __half2 h[4]; } pk;
            pk.h[0] = __floats2half2_rn(v[0], v[1]);
            pk.h[1] = __floats2half2_rn(v[2], v[3]);
            pk.h[2] = __floats2half2_rn(v[4], v[5]);
            pk.h[3] = __floats2half2_rn(v[6], v[7]);
            *(uint4*)&g_h2h[(size_t)gm * HID + half * 32 + q * 8] = pk.u;
            #pragma unroll
            for (int jj = 0; jj < 8; jj++) {
                sp = fmaf(v[jj], s_att[0][half * 32 + q * 8 + jj], sp);
                dp = fmaf(v[jj], s_att[1][half * 32 + q * 8 + jj], dp);
            }
        }
    }
    sp += __shfl_xor_sync(0xffffffffu, sp, 1);
    dp += __shfl_xor_sync(0xffffffffu, dp, 1);
    if (gm < NN && half == 0) { g_as2[gm] = sp; g_ad2[gm] = dp; }
}

__device__ __forceinline__ float lrelu(float e) {
    return e > 0.f ? e : NEG_SLOPE * e;
}

// ---------------- gather1: block per dst, warp h = head h ------------------
// Lane-parallel scores/exp (one MUFU instruction per 32 edges), shfl-broadcast
// weights into the message loop. den reduced once at the end (fixed order).
__global__ void __launch_bounds__(256, 8)
k_gather1(const float* __restrict__ bias) {
    int d = blockIdx.x;
    int h = threadIdx.x >> 5, lane = threadIdx.x & 31;
    int r0 = g_rowptr[d], r1 = g_rowptr[d + 1];
    float ad = g_ad1[d * H1 + h];

    float denp = 0.f, a0 = 0.f, a1 = 0.f;
    for (int base = r0; base < r1; base += 32) {
        int n = min(32, r1 - base);
        int sv = 0; float w = 0.f;
        if (base + lane < r1) {
            sv = __ldg(&g_esrc[base + lane]);
            float e = lrelu(__ldg(&g_as1[sv * H1 + h]) + ad);
            w = __expf(e);
        }
        denp += w;
        #pragma unroll 4
        for (int j = 0; j < n; j++) {
            int   s  = __shfl_sync(0xffffffffu, sv, j);
            float wj = __shfl_sync(0xffffffffu, w, j);
            __half2 v = ((const __half2*)(g_h1h + (size_t)s * C1 + h * HID))[lane];
            float2 vf = __half22float2(v);
            a0 = fmaf(wj, vf.x, a0);
            a1 = fmaf(wj, vf.y, a1);
        }
    }
    float den = denp;
    #pragma unroll
    for (int off = 16; off; off >>= 1) den += __shfl_xor_sync(0xffffffffu, den, off);

    float inv = 1.f / (den + EPS);
    int c0 = h * HID + 2 * lane;
    float o0 = a0 * inv + bias[c0];
    float o1 = a1 * inv + bias[c0 + 1];
    o0 = o0 > 0.f ? o0 : expm1f(o0);
    o1 = o1 > 0.f ? o1 : expm1f(o1);
    *(__half2*)&g_hah[(size_t)d * C1 + c0] = __floats2half2_rn(o0, o1);
}

// ---------------- gather2: warp per dst ------------------------------------
__global__ void __launch_bounds__(256, 8)
k_gather2(const float* __restrict__ bias) {
    int d = (blockIdx.x * blockDim.x + threadIdx.x) >> 5;
    int lane = threadIdx.x & 31;
    if (d >= NN) return;
    float ad = g_ad2[d];
    int r0 = g_rowptr[d], r1 = g_rowptr[d + 1];

    float denp = 0.f, a0 = 0.f, a1 = 0.f;
    for (int base = r0; base < r1; base += 32) {
        int n = min(32, r1 - base);
        int sv = 0; float w = 0.f;
        if (base + lane < r1) {
            sv = __ldg(&g_esrc[base + lane]);
            float e = lrelu(__ldg(&g_as2[sv]) + ad);
            w = __expf(e);
        }
        denp += w;
        #pragma unroll 4
        for (int j = 0; j < n; j++) {
            int   s  = __shfl_sync(0xffffffffu, sv, j);
            float wj = __shfl_sync(0xffffffffu, w, j);
            __half2 v = ((const __half2*)(g_h2h + (size_t)s * HID))[lane];
            float2 vf = __half22float2(v);
            a0 = fmaf(wj, vf.x, a0);
            a1 = fmaf(wj, vf.y, a1);
        }
    }
    float den = denp;
    #pragma unroll
    for (int off = 16; off; off >>= 1) den += __shfl_xor_sync(0xffffffffu, den, off);

    float inv = 1.f / (den + EPS);
    int c0 = 2 * lane;
    g_out2[(size_t)d * HID + c0]     = a0 * inv + bias[c0];
    g_out2[(size_t)d * HID + c0 + 1] = a1 * inv + bias[c0 + 1];
}

// ---------------- global mean pool + final linear ----------------
__device__ __forceinline__ int lb32(const int* a, int n, int v) {
    int lo = 0, hi = n;
    while (lo < hi) { int mid = (lo + hi) >> 1; if (a[mid] < v) lo = mid + 1; else hi = mid; }
    return lo;
}

__global__ void k_pool(const int* __restrict__ batch,
                       const float* __restrict__ linW,
                       const float* __restrict__ linb,
                       float* __restrict__ out) {
    __shared__ float sm[256];
    int g = blockIdx.x;
    int lo = lb32(batch, NN, g);
    int hi = lb32(batch, NN, g + 1);
    int c = threadIdx.x & 63;
    int sub = threadIdx.x >> 6;
    float acc = 0.f;
    for (int n = lo + sub; n < hi; n += 4)
        acc += g_out2[(size_t)n * HID + c];
    sm[threadIdx.x] = acc;
    __syncthreads();
    if (threadIdx.x < 64) {
        float v = sm[threadIdx.x] + sm[threadIdx.x + 64] + sm[threadIdx.x + 128] + sm[threadIdx.x + 192];
        sm[threadIdx.x] = v * linW[threadIdx.x];
    }
    __syncthreads();
    if (threadIdx.x < 32) {
        float v = sm[threadIdx.x] + sm[threadIdx.x + 32];
        #pragma unroll
        for (int off = 16; off; off >>= 1) v += __shfl_down_sync(0xffffffffu, v, off);
        if (threadIdx.x == 0) {
            float cnt = (float)(hi - lo);
            out[g] = v / fmaxf(cnt, 1.f) + linb[0];
        }
    }
}

// ---------------- launch ----------------
extern "C" void kernel_launch(void* const* d_in, const int* in_sizes, int n_in,
                              void* d_out, int out_size) {
    const float* x     = (const float*)d_in[0];
    const int*   ei    = (const int*)d_in[1];
    const int*   batch = (const int*)d_in[2];
    const float* W1   = (const float*)d_in[3];
    const float* as1  = (const float*)d_in[4];
    const float* ad1  = (const float*)d_in[5];
    const float* b1   = (const float*)d_in[6];
    const float* W2   = (const float*)d_in[7];
    const float* as2  = (const float*)d_in[8];
    const float* ad2  = (const float*)d_in[9];
    const float* b2   = (const float*)d_in[10];
    const float* linW = (const float*)d_in[11];
    const float* linb = (const float*)d_in[12];
    float* out = (float*)d_out;
    (void)in_sizes; (void)n_in; (void)out_size;

    cudaFuncSetAttribute(k_gemm1, cudaFuncAttributeMaxDynamicSharedMemorySize, 69632);
    cudaFuncSetAttribute(k_gemm2, cudaFuncAttributeMaxDynamicSharedMemorySize, 55296);

    // conversions (+zero) and CSR build
    k_cvtx<<<(NN * FIN / 8 + 255) / 256, 256>>>(x);
    k_cvtw<<<(12288 + 255) / 256, 256>>>(W1, W2);
    k_count<<<(ET + 255) / 256, 256>>>(ei);
    k_scan_a<<<SCAN_NB, SCAN_B>>>();
    k_scan_b<<<1, 32>>>();
    k_scan_c<<<SCAN_NB, SCAN_B>>>();
    k_scatter<<<(ET + 255) / 256, 256>>>(ei);
    k_sortseg<<<(NN + 255) / 256, 256>>>();

    // layer 1
    {
        dim3 grid(C1 / 128, (NN + 127) / 128);
        k_gemm1<<<grid, 256, 69632>>>(as1, ad1);
    }
    k_gather1<<<NN, 256>>>(b1);

    // layer 2
    k_gemm2<<<(NN + 127) / 128, 256, 55296>>>(as2, ad2);
    k_gather2<<<(NN + 7) / 8, 256>>>(b2);

    // pool + linear
    k_pool<<<GG, 256>>>(batch, linW, linb, out);
}